// round 3
// baseline (speedup 1.0000x reference)
#include <cuda_runtime.h>
#include <math.h>
#include <stdint.h>

#define NODES   50000
#define HID     128
#define MTILE   64
#define NBLOCKS ((NODES + MTILE - 1) / MTILE)   // 782

// strides in uint2 (8-byte) units; must be >=128 and ==4 (mod 16) for
// phase-conflict-free LDS.64 (bank-pair = stride*row + col injective per
// 16-lane phase)
#define W_S2 132
#define H_S2 132

// Scratch (allocation-free rule: __device__ globals)
__device__ float g_gsq[NODES];   // g_phi(v,a)^2 per node
__device__ float g_msg[NODES];   // aggregated messages per node

// ---------------------------------------------------------------------------
__global__ void zero_msg_kernel() {
    int i = blockIdx.x * blockDim.x + threadIdx.x;
    if (i < NODES) g_msg[i] = 0.0f;
}

// ---------------------------------------------------------------------------
// tf32 helpers: split fp32 into hi(tf32) + lo(tf32 of residual).
// tf32x3: A*B ~= Ahi*Bhi + Ahi*Blo + Alo*Bhi  (error ~2^-22)
// ---------------------------------------------------------------------------
__device__ __forceinline__ uint32_t f2tf(float x) {
    uint32_t r;
    asm("cvt.rna.tf32.f32 %0, %1;" : "=r"(r) : "f"(x));
    return r;
}
__device__ __forceinline__ uint2 split_tf(float x) {
    uint2 r;
    r.x = f2tf(x);                               // hi
    r.y = f2tf(x - __uint_as_float(r.x));        // lo
    return r;
}
__device__ __forceinline__ void mma8(float* c, const uint32_t* a, const uint32_t* b) {
    asm volatile(
        "mma.sync.aligned.m16n8k8.row.col.f32.tf32.tf32.f32 "
        "{%0,%1,%2,%3}, {%4,%5,%6,%7}, {%8,%9}, {%0,%1,%2,%3};"
        : "+f"(c[0]), "+f"(c[1]), "+f"(c[2]), "+f"(c[3])
        : "r"(a[0]), "r"(a[1]), "r"(a[2]), "r"(a[3]),
          "r"(b[0]), "r"(b[1]));
}

// ---------------------------------------------------------------------------
// Fused 3-layer MLP over a tile of 64 nodes.
//   layer0 scalar -> tanh -> split -> Hsp (uint2 hi/lo plane)
//   W1 staged + split once -> Wsp (uint2 hi/lo plane)
//   layer1 mainloop: pure LDS.64 + 3x HMMA (tf32x3), no conversions
//   layer2 + tanh epilogue reduced from C fragments
// ---------------------------------------------------------------------------
template <int IN_DIM, bool SQUARE>
__global__ void __launch_bounds__(256, 1) mlp_mma_kernel(
    const float* __restrict__ v,
    const float* __restrict__ a,
    const float* __restrict__ exc,
    const float* __restrict__ w0, const float* __restrict__ b0,
    const float* __restrict__ w1, const float* __restrict__ b1,
    const float* __restrict__ w2, const float* __restrict__ b2,
    float* __restrict__ out)
{
    extern __shared__ float sm[];
    uint2* Wsp = (uint2*)sm;                         // HID * W_S2 uint2
    uint2* Hsp = Wsp + HID * W_S2;                   // MTILE * H_S2 uint2
    float* xs  = (float*)(Hsp + MTILE * H_S2);       // MTILE * IN_DIM
    float* w0s = xs + MTILE * 5;                     // IN_DIM * HID
    float* b0s = w0s + 5 * HID;
    float* b1s = b0s + HID;
    float* w2s = b1s + HID;
    float* red = w2s + HID;                          // MTILE * 2

    const int t    = threadIdx.x;
    const int base = blockIdx.x * MTILE;

    // ---- stage + pre-split W1 (hi/lo) ----
    {
        const float4* s4 = (const float4*)w1;
        for (int i = t; i < HID * HID / 4; i += 256) {
            float4 x4 = s4[i];
            int k = (i * 4) >> 7, n = (i * 4) & 127;
            uint2* d = &Wsp[k * W_S2 + n];
            d[0] = split_tf(x4.x);
            d[1] = split_tf(x4.y);
            d[2] = split_tf(x4.z);
            d[3] = split_tf(x4.w);
        }
    }
    for (int i = t; i < IN_DIM * HID; i += 256) w0s[i] = w0[i];
    if (t < HID) { b0s[t] = b0[t]; b1s[t] = b1[t]; w2s[t] = w2[t]; }
    if (t < MTILE) {
        int ng = base + t;
        bool ok = ng < NODES;
        xs[t * IN_DIM + 0] = ok ? v[ng]         : 0.0f;
        xs[t * IN_DIM + 1] = ok ? a[2 * ng]     : 0.0f;
        xs[t * IN_DIM + 2] = ok ? a[2 * ng + 1] : 0.0f;
        if (IN_DIM == 5) {
            xs[t * IN_DIM + 3] = ok ? g_msg[ng] : 0.0f;
            xs[t * IN_DIM + 4] = ok ? exc[ng]   : 0.0f;
        }
    }
    __syncthreads();

    // ---- layer 0: H0 = tanh(x @ w0 + b0), split on the way out ----
    for (int i = t; i < MTILE * HID; i += 256) {
        int node = i >> 7, hid = i & 127;
        float acc = b0s[hid];
        #pragma unroll
        for (int d = 0; d < IN_DIM; d++)
            acc += xs[node * IN_DIM + d] * w0s[d * HID + hid];
        Hsp[node * H_S2 + hid] = split_tf(tanhf(acc));
    }
    __syncthreads();

    // ---- layer 1: 64x128x128 GEMM, tf32x3, pure LDS+MMA mainloop ----
    const int w    = t >> 5, lane = t & 31;
    const int mt   = w & 3,  nh   = w >> 2;
    const int r0   = lane >> 2, q = lane & 3;

    float C[8][4];
    #pragma unroll
    for (int i = 0; i < 8; i++) {
        C[i][0] = 0.f; C[i][1] = 0.f; C[i][2] = 0.f; C[i][3] = 0.f;
    }

    const uint2* Arow0 = &Hsp[(mt * 16 + r0) * H_S2];
    const uint2* Arow1 = Arow0 + 8 * H_S2;

    #pragma unroll 2
    for (int ks = 0; ks < 16; ks++) {
        const int k0 = ks * 8;
        uint2 a0 = Arow0[k0 + q];
        uint2 a1 = Arow1[k0 + q];
        uint2 a2 = Arow0[k0 + q + 4];
        uint2 a3 = Arow1[k0 + q + 4];
        uint32_t Ahi[4] = {a0.x, a1.x, a2.x, a3.x};
        uint32_t Alo[4] = {a0.y, a1.y, a2.y, a3.y};
        #pragma unroll
        for (int nt = 0; nt < 8; nt++) {
            const int col = nh * 64 + nt * 8 + r0;
            uint2 b0v = Wsp[(k0 + q)     * W_S2 + col];
            uint2 b1v = Wsp[(k0 + q + 4) * W_S2 + col];
            uint32_t Bhi[2] = {b0v.x, b1v.x};
            uint32_t Blo[2] = {b0v.y, b1v.y};
            mma8(C[nt], Alo, Bhi);
            mma8(C[nt], Ahi, Blo);
            mma8(C[nt], Ahi, Bhi);
        }
    }

    // ---- layer 2 epilogue: out = sum_c tanh(C+b1)[c] * w2[c] + b2 ----
    float p0 = 0.f, p1 = 0.f;
    #pragma unroll
    for (int nt = 0; nt < 8; nt++) {
        const int c0 = nh * 64 + nt * 8 + q * 2;
        const float bb0 = b1s[c0], bb1 = b1s[c0 + 1];
        const float ww0 = w2s[c0], ww1 = w2s[c0 + 1];
        p0 += tanhf(C[nt][0] + bb0) * ww0 + tanhf(C[nt][1] + bb1) * ww1;
        p1 += tanhf(C[nt][2] + bb0) * ww0 + tanhf(C[nt][3] + bb1) * ww1;
    }
    p0 += __shfl_xor_sync(0xffffffffu, p0, 1);
    p0 += __shfl_xor_sync(0xffffffffu, p0, 2);
    p1 += __shfl_xor_sync(0xffffffffu, p1, 1);
    p1 += __shfl_xor_sync(0xffffffffu, p1, 2);
    if (q == 0) {
        red[(mt * 16 + r0)     * 2 + nh] = p0;
        red[(mt * 16 + r0 + 8) * 2 + nh] = p1;
    }
    __syncthreads();

    if (t < MTILE) {
        int ng = base + t;
        if (ng < NODES) {
            float s = red[t * 2] + red[t * 2 + 1] + b2[0];
            if (SQUARE) g_gsq[ng] = s * s;
            else        out[ng]   = s;
        }
    }
}

// ---------------------------------------------------------------------------
// Edge pass: msg[dst] += W[e] * gsq[src]
// ---------------------------------------------------------------------------
__global__ void edge_kernel(const int* __restrict__ src,
                            const int* __restrict__ dst,
                            const float* __restrict__ W,
                            int n_edges)
{
    int i = blockIdx.x * blockDim.x + threadIdx.x;
    if (i < n_edges) {
        const float m = W[i] * g_gsq[src[i]];
        atomicAdd(&g_msg[dst[i]], m);
    }
}

// ---------------------------------------------------------------------------
extern "C" void kernel_launch(void* const* d_in, const int* in_sizes, int n_in,
                              void* d_out, int out_size)
{
    const float* v    = (const float*)d_in[0];
    const float* exc  = (const float*)d_in[1];
    const int*   esrc = (const int*)  d_in[2];
    const int*   edst = (const int*)  d_in[3];
    const float* a    = (const float*)d_in[4];
    const float* W    = (const float*)d_in[5];
    const float* g0w  = (const float*)d_in[6];
    const float* g0b  = (const float*)d_in[7];
    const float* g1w  = (const float*)d_in[8];
    const float* g1b  = (const float*)d_in[9];
    const float* g2w  = (const float*)d_in[10];
    const float* g2b  = (const float*)d_in[11];
    const float* f0w  = (const float*)d_in[12];
    const float* f0b  = (const float*)d_in[13];
    const float* f1w  = (const float*)d_in[14];
    const float* f1b  = (const float*)d_in[15];
    const float* f2w  = (const float*)d_in[16];
    const float* f2b  = (const float*)d_in[17];
    float*       out  = (float*)d_out;

    const int n_edges = in_sizes[2];

    const int smem_bytes =
        (HID * W_S2 + MTILE * H_S2) * 8 +
        (MTILE * 5 + 5 * HID + 3 * HID + MTILE * 2) * 4;   // ~209 KB

    cudaFuncSetAttribute(mlp_mma_kernel<3, true>,
                         cudaFuncAttributeMaxDynamicSharedMemorySize, smem_bytes);
    cudaFuncSetAttribute(mlp_mma_kernel<5, false>,
                         cudaFuncAttributeMaxDynamicSharedMemorySize, smem_bytes);

    zero_msg_kernel<<<(NODES + 255) / 256, 256>>>();

    mlp_mma_kernel<3, true><<<NBLOCKS, 256, smem_bytes>>>(
        v, a, nullptr, g0w, g0b, g1w, g1b, g2w, g2b, nullptr);

    edge_kernel<<<(n_edges + 255) / 256, 256>>>(esrc, edst, W, n_edges);

    mlp_mma_kernel<5, false><<<NBLOCKS, 256, smem_bytes>>>(
        v, a, exc, f0w, f0b, f1w, f1b, f2w, f2b, out);
}

// round 5
// speedup vs baseline: 1.7415x; 1.7415x over previous
#include <cuda_runtime.h>
#include <math.h>
#include <stdint.h>

#define NODES   50000
#define HID     128
#define MTILE   128
#define NTILES  ((NODES + MTILE - 1) / MTILE)   // 391
#define THREADS 512
#define GRID    148

// W pre-split plane: stride in uint2 units, ==4 (mod 16) -> conflict-free LDS.64
#define W_S2 132
// H plain-float plane: stride in floats, ==4 (mod 32) -> conflict-free LDS.32
#define H_SF 132

// Scratch (allocation-free rule: __device__ globals)
__device__ float g_gsq[NODES];   // g_phi(v,a)^2 per node
__device__ float g_msg[NODES];   // aggregated messages per node

// ---------------------------------------------------------------------------
// tf32 helpers: split fp32 into hi(tf32) + lo(tf32 of residual).
// tf32x3: A*B ~= Ahi*Bhi + Ahi*Blo + Alo*Bhi  (error ~2^-22)
// ---------------------------------------------------------------------------
__device__ __forceinline__ uint32_t f2tf(float x) {
    uint32_t r;
    asm("cvt.rna.tf32.f32 %0, %1;" : "=r"(r) : "f"(x));
    return r;
}
__device__ __forceinline__ uint2 split_tf(float x) {
    uint2 r;
    r.x = f2tf(x);
    r.y = f2tf(x - __uint_as_float(r.x));
    return r;
}
__device__ __forceinline__ void mma8(float* c, const uint32_t* a, const uint32_t* b) {
    asm volatile(
        "mma.sync.aligned.m16n8k8.row.col.f32.tf32.tf32.f32 "
        "{%0,%1,%2,%3}, {%4,%5,%6,%7}, {%8,%9}, {%0,%1,%2,%3};"
        : "+f"(c[0]), "+f"(c[1]), "+f"(c[2]), "+f"(c[3])
        : "r"(a[0]), "r"(a[1]), "r"(a[2]), "r"(a[3]),
          "r"(b[0]), "r"(b[1]));
}

// ---------------------------------------------------------------------------
// Persistent fused 3-layer MLP.
//   Stage + pre-split W1 ONCE per block, then grid-stride over 128-node tiles.
//   layer0 scalar -> tanh -> Hs (plain fp32)
//   layer1: LDS A (split in regs) + LDS.64 pre-split B + 3x HMMA (tf32x3)
//   layer2 + tanh epilogue via shfl reduce
// 16 warps: warp w -> m-tile (w&7) [16 rows], n-half (w>>3) [64 cols]
// ---------------------------------------------------------------------------
template <int IN_DIM, bool SQUARE>
__global__ void __launch_bounds__(THREADS, 1) mlp_mma_kernel(
    const float* __restrict__ v,
    const float* __restrict__ a,
    const float* __restrict__ exc,
    const float* __restrict__ w0, const float* __restrict__ b0,
    const float* __restrict__ w1, const float* __restrict__ b1,
    const float* __restrict__ w2, const float* __restrict__ b2,
    float* __restrict__ out)
{
    extern __shared__ float sm[];
    uint2* Wsp = (uint2*)sm;                       // HID * W_S2 uint2   (135 KB)
    float* Hs  = (float*)(Wsp + HID * W_S2);       // MTILE * H_SF       (67.5 KB)
    float* xs  = Hs + MTILE * H_SF;                // MTILE * IN_DIM
    float* w0s = xs + MTILE * 5;                   // IN_DIM * HID
    float* b0s = w0s + 5 * HID;
    float* b1s = b0s + HID;
    float* w2s = b1s + HID;
    float* red = w2s + HID;                        // MTILE * 2

    const int t    = threadIdx.x;
    const int wrp  = t >> 5, lane = t & 31;
    const int mt   = wrp & 7, nh = wrp >> 3;
    const int r0   = lane >> 2, q = lane & 3;

    // ---- one-time staging: W1 (split), w0, biases ----
    {
        const float4* s4 = (const float4*)w1;
        for (int i = t; i < HID * HID / 4; i += THREADS) {
            float4 x4 = s4[i];
            int k = (i * 4) >> 7, n = (i * 4) & 127;
            uint2* d = &Wsp[k * W_S2 + n];
            d[0] = split_tf(x4.x);
            d[1] = split_tf(x4.y);
            d[2] = split_tf(x4.z);
            d[3] = split_tf(x4.w);
        }
    }
    for (int i = t; i < IN_DIM * HID; i += THREADS) w0s[i] = w0[i];  // FIX: loop, not if
    if (t < HID) { b0s[t] = b0[t]; b1s[t] = b1[t]; w2s[t] = w2[t]; }
    const float b2v = b2[0];
    __syncthreads();

    for (int tile = blockIdx.x; tile < NTILES; tile += GRID) {
        const int base = tile * MTILE;

        // ---- load node inputs ----
        if (t < MTILE) {
            int ng = base + t;
            bool ok = ng < NODES;
            xs[t * IN_DIM + 0] = ok ? v[ng]         : 0.0f;
            xs[t * IN_DIM + 1] = ok ? a[2 * ng]     : 0.0f;
            xs[t * IN_DIM + 2] = ok ? a[2 * ng + 1] : 0.0f;
            if (IN_DIM == 5) {
                xs[t * IN_DIM + 3] = ok ? g_msg[ng] : 0.0f;
                xs[t * IN_DIM + 4] = ok ? exc[ng]   : 0.0f;
            }
        }
        __syncthreads();

        // ---- layer 0: H0 = tanh(x @ w0 + b0) ----
        #pragma unroll 4
        for (int i = t; i < MTILE * HID; i += THREADS) {
            int node = i >> 7, hid = i & 127;
            float acc = b0s[hid];
            #pragma unroll
            for (int d = 0; d < IN_DIM; d++)
                acc += xs[node * IN_DIM + d] * w0s[d * HID + hid];
            Hs[node * H_SF + hid] = tanhf(acc);
        }
        __syncthreads();

        // ---- layer 1: 128x128x128 GEMM tile, tf32x3 ----
        float C[8][4];
        #pragma unroll
        for (int i = 0; i < 8; i++) {
            C[i][0] = 0.f; C[i][1] = 0.f; C[i][2] = 0.f; C[i][3] = 0.f;
        }

        const float* Arow0 = &Hs[(mt * 16 + r0) * H_SF];
        const float* Arow1 = Arow0 + 8 * H_SF;

        #pragma unroll 2
        for (int ks = 0; ks < 16; ks++) {
            const int k0 = ks * 8;
            uint2 sa0 = split_tf(Arow0[k0 + q]);
            uint2 sa1 = split_tf(Arow1[k0 + q]);
            uint2 sa2 = split_tf(Arow0[k0 + q + 4]);
            uint2 sa3 = split_tf(Arow1[k0 + q + 4]);
            uint32_t Ahi[4] = {sa0.x, sa1.x, sa2.x, sa3.x};
            uint32_t Alo[4] = {sa0.y, sa1.y, sa2.y, sa3.y};
            #pragma unroll
            for (int nt = 0; nt < 8; nt++) {
                const int col = nh * 64 + nt * 8 + r0;
                uint2 b0v = Wsp[(k0 + q)     * W_S2 + col];
                uint2 b1v = Wsp[(k0 + q + 4) * W_S2 + col];
                uint32_t Bhi[2] = {b0v.x, b1v.x};
                uint32_t Blo[2] = {b0v.y, b1v.y};
                mma8(C[nt], Alo, Bhi);
                mma8(C[nt], Ahi, Blo);
                mma8(C[nt], Ahi, Bhi);
            }
        }

        // ---- layer 2 epilogue ----
        float p0 = 0.f, p1 = 0.f;
        #pragma unroll
        for (int nt = 0; nt < 8; nt++) {
            const int c0 = nh * 64 + nt * 8 + q * 2;
            const float bb0 = b1s[c0], bb1 = b1s[c0 + 1];
            const float ww0 = w2s[c0], ww1 = w2s[c0 + 1];
            p0 += tanhf(C[nt][0] + bb0) * ww0 + tanhf(C[nt][1] + bb1) * ww1;
            p1 += tanhf(C[nt][2] + bb0) * ww0 + tanhf(C[nt][3] + bb1) * ww1;
        }
        p0 += __shfl_xor_sync(0xffffffffu, p0, 1);
        p0 += __shfl_xor_sync(0xffffffffu, p0, 2);
        p1 += __shfl_xor_sync(0xffffffffu, p1, 1);
        p1 += __shfl_xor_sync(0xffffffffu, p1, 2);
        if (q == 0) {
            red[(mt * 16 + r0)     * 2 + nh] = p0;
            red[(mt * 16 + r0 + 8) * 2 + nh] = p1;
        }
        __syncthreads();

        if (t < MTILE) {
            int ng = base + t;
            if (ng < NODES) {
                float s = red[t * 2] + red[t * 2 + 1] + b2v;
                if (SQUARE) {
                    g_gsq[ng] = s * s;
                    g_msg[ng] = 0.0f;   // fused zero for the edge pass
                } else {
                    out[ng] = s;
                }
            }
        }
        __syncthreads();   // protect xs/Hs/red before next tile
    }
}

// ---------------------------------------------------------------------------
// Edge pass: msg[dst] += W[e] * gsq[src]
// ---------------------------------------------------------------------------
__global__ void edge_kernel(const int* __restrict__ src,
                            const int* __restrict__ dst,
                            const float* __restrict__ W,
                            int n_edges)
{
    int i = blockIdx.x * blockDim.x + threadIdx.x;
    if (i < n_edges) {
        const float m = W[i] * g_gsq[src[i]];
        atomicAdd(&g_msg[dst[i]], m);
    }
}

// ---------------------------------------------------------------------------
extern "C" void kernel_launch(void* const* d_in, const int* in_sizes, int n_in,
                              void* d_out, int out_size)
{
    const float* v    = (const float*)d_in[0];
    const float* exc  = (const float*)d_in[1];
    const int*   esrc = (const int*)  d_in[2];
    const int*   edst = (const int*)  d_in[3];
    const float* a    = (const float*)d_in[4];
    const float* W    = (const float*)d_in[5];
    const float* g0w  = (const float*)d_in[6];
    const float* g0b  = (const float*)d_in[7];
    const float* g1w  = (const float*)d_in[8];
    const float* g1b  = (const float*)d_in[9];
    const float* g2w  = (const float*)d_in[10];
    const float* g2b  = (const float*)d_in[11];
    const float* f0w  = (const float*)d_in[12];
    const float* f0b  = (const float*)d_in[13];
    const float* f1w  = (const float*)d_in[14];
    const float* f1b  = (const float*)d_in[15];
    const float* f2w  = (const float*)d_in[16];
    const float* f2b  = (const float*)d_in[17];
    float*       out  = (float*)d_out;

    const int n_edges = in_sizes[2];

    const int smem_bytes =
        HID * W_S2 * 8 + MTILE * H_SF * 4 +
        (MTILE * 5 + 5 * HID + 3 * HID + MTILE * 2) * 4;   // ~207 KB

    cudaFuncSetAttribute(mlp_mma_kernel<3, true>,
                         cudaFuncAttributeMaxDynamicSharedMemorySize, smem_bytes);
    cudaFuncSetAttribute(mlp_mma_kernel<5, false>,
                         cudaFuncAttributeMaxDynamicSharedMemorySize, smem_bytes);

    mlp_mma_kernel<3, true><<<GRID, THREADS, smem_bytes>>>(
        v, a, nullptr, g0w, g0b, g1w, g1b, g2w, g2b, nullptr);

    edge_kernel<<<(n_edges + 255) / 256, 256>>>(esrc, edst, W, n_edges);

    mlp_mma_kernel<5, false><<<GRID, THREADS, smem_bytes>>>(
        v, a, exc, f0w, f0b, f1w, f1b, f2w, f2b, out);
}

// round 6
// speedup vs baseline: 2.2475x; 1.2905x over previous
#include <cuda_runtime.h>
#include <cuda_bf16.h>
#include <math.h>
#include <stdint.h>

#define NODES   50000
#define HID     128
#define MTILE   128
#define NTILES  ((NODES + MTILE - 1) / MTILE)   // 391
#define THREADS 512
#define GRID    148

// plane strides in uint2 units: ==4 (mod 16) -> conflict-free LDS.64
// (16-lane phase: addr mod 16 = 4*r + q, injective)
#define H_S2U 68
#define W_S2U 68

// Scratch (allocation-free rule: __device__ globals)
__device__ float g_gsq[NODES];
__device__ float g_msg[NODES];

// ---------------------------------------------------------------------------
// bf16x3 helpers: x ~ hi + lo (bf16 each). A*B ~= Ahi*Bhi + Ahi*Blo + Alo*Bhi
// dropped term lo*lo ~ 2^-16 relative.
// ---------------------------------------------------------------------------
__device__ __forceinline__ float bfround(float x) {
    return __bfloat162float(__float2bfloat16(x));
}
// pack two floats as bf16x2; f_even -> low 16 bits (k even), f_odd -> high
__device__ __forceinline__ uint32_t bfpack(float f_even, float f_odd) {
    uint32_t r;
    asm("cvt.rn.bf16x2.f32 %0, %1, %2;" : "=r"(r) : "f"(f_odd), "f"(f_even));
    return r;
}
__device__ __forceinline__ void mma16(float* c, const uint32_t* a, const uint32_t* b) {
    asm volatile(
        "mma.sync.aligned.m16n8k16.row.col.f32.bf16.bf16.f32 "
        "{%0,%1,%2,%3}, {%4,%5,%6,%7}, {%8,%9}, {%0,%1,%2,%3};"
        : "+f"(c[0]), "+f"(c[1]), "+f"(c[2]), "+f"(c[3])
        : "r"(a[0]), "r"(a[1]), "r"(a[2]), "r"(a[3]),
          "r"(b[0]), "r"(b[1]));
}

// ---------------------------------------------------------------------------
// Persistent fused 3-layer MLP (bf16x3 tensor-core middle layer).
//   W1 transposed+split once per block -> Wt2 plane {hi2,lo2} (n-major)
//   layer0 scalar -> tanh -> split -> Hs2 plane {hi2,lo2} (row-major)
//   layer1 mainloop: pure LDS.64 + 3x HMMA.16816 per (ks,nt)
//   layer2 + tanh epilogue via shfl reduce
// 16 warps: warp w -> m-tile (w&7) [16 rows], n-half (w>>3) [64 cols]
// ---------------------------------------------------------------------------
template <int IN_DIM, bool SQUARE>
__global__ void __launch_bounds__(THREADS, 1) mlp_mma_kernel(
    const float* __restrict__ v,
    const float* __restrict__ a,
    const float* __restrict__ exc,
    const float* __restrict__ w0, const float* __restrict__ b0,
    const float* __restrict__ w1, const float* __restrict__ b1,
    const float* __restrict__ w2, const float* __restrict__ b2,
    float* __restrict__ out)
{
    extern __shared__ float sm[];
    uint2* Wt2 = (uint2*)sm;                       // HID * W_S2U uint2  (69.6 KB)
    uint2* Hs2 = Wt2 + HID * W_S2U;                // MTILE * H_S2U      (69.6 KB)
    float* xs  = (float*)(Hs2 + MTILE * H_S2U);    // MTILE * IN_DIM
    float* w0s = xs + MTILE * 5;                   // IN_DIM * HID
    float* b0s = w0s + 5 * HID;
    float* b1s = b0s + HID;
    float* w2s = b1s + HID;
    float* red = w2s + HID;                        // MTILE * 2

    const int t    = threadIdx.x;
    const int wrp  = t >> 5, lane = t & 31;
    const int mt   = wrp & 7, nh = wrp >> 3;
    const int r0   = lane >> 2, q = lane & 3;

    // ---- one-time staging: W1^T split into bf16 hi/lo planes ----
    for (int i = t; i < HID * HID / 2; i += THREADS) {
        int j = i >> 7;          // kpair 0..63
        int n = i & 127;         // output col (coalesced across threads)
        float e  = w1[(2 * j)     * HID + n];   // k even
        float o  = w1[(2 * j + 1) * HID + n];   // k odd
        float eh = bfround(e), oh = bfround(o);
        Wt2[n * W_S2U + j] = make_uint2(bfpack(eh, oh),
                                        bfpack(e - eh, o - oh));
    }
    for (int i = t; i < IN_DIM * HID; i += THREADS) w0s[i] = w0[i];
    if (t < HID) { b0s[t] = b0[t]; b1s[t] = b1[t]; w2s[t] = w2[t]; }
    const float b2v = b2[0];
    __syncthreads();

    for (int tile = blockIdx.x; tile < NTILES; tile += GRID) {
        const int base = tile * MTILE;

        // ---- load node inputs ----
        if (t < MTILE) {
            int ng = base + t;
            bool ok = ng < NODES;
            xs[t * IN_DIM + 0] = ok ? v[ng]         : 0.0f;
            xs[t * IN_DIM + 1] = ok ? a[2 * ng]     : 0.0f;
            xs[t * IN_DIM + 2] = ok ? a[2 * ng + 1] : 0.0f;
            if (IN_DIM == 5) {
                xs[t * IN_DIM + 3] = ok ? g_msg[ng] : 0.0f;
                xs[t * IN_DIM + 4] = ok ? exc[ng]   : 0.0f;
            }
        }
        __syncthreads();

        // ---- layer 0: H0 = tanh(x @ w0 + b0), split+pack to bf16 planes ----
        #pragma unroll 4
        for (int i = t; i < MTILE * HID / 2; i += THREADS) {
            int node = i >> 6, j = i & 63;          // j = hid pair
            const float* x = &xs[node * IN_DIM];
            float acc0 = b0s[2 * j], acc1 = b0s[2 * j + 1];
            #pragma unroll
            for (int d = 0; d < IN_DIM; d++) {
                acc0 += x[d] * w0s[d * HID + 2 * j];
                acc1 += x[d] * w0s[d * HID + 2 * j + 1];
            }
            float h0 = tanhf(acc0), h1 = tanhf(acc1);
            float h0h = bfround(h0), h1h = bfround(h1);
            Hs2[node * H_S2U + j] = make_uint2(bfpack(h0h, h1h),
                                               bfpack(h0 - h0h, h1 - h1h));
        }
        __syncthreads();

        // ---- layer 1: 128x128x128 GEMM tile, bf16x3, pure LDS+MMA ----
        float C[8][4];
        #pragma unroll
        for (int i = 0; i < 8; i++) {
            C[i][0] = 0.f; C[i][1] = 0.f; C[i][2] = 0.f; C[i][3] = 0.f;
        }

        const uint2* Arow0 = &Hs2[(mt * 16 + r0) * H_S2U];
        const uint2* Arow1 = Arow0 + 8 * H_S2U;

        #pragma unroll
        for (int ks = 0; ks < 8; ks++) {            // K = 8 * 16
            const int jb = ks * 8;
            uint2 a0 = Arow0[jb + q];
            uint2 a1 = Arow1[jb + q];
            uint2 a2 = Arow0[jb + q + 4];
            uint2 a3 = Arow1[jb + q + 4];
            uint32_t Ahi[4] = {a0.x, a1.x, a2.x, a3.x};
            uint32_t Alo[4] = {a0.y, a1.y, a2.y, a3.y};
            #pragma unroll
            for (int nt = 0; nt < 8; nt++) {
                const uint2* Bp = &Wt2[(nh * 64 + nt * 8 + r0) * W_S2U + jb];
                uint2 b0v = Bp[q];
                uint2 b1v = Bp[q + 4];
                uint32_t Bhi[2] = {b0v.x, b1v.x};
                uint32_t Blo[2] = {b0v.y, b1v.y};
                mma16(C[nt], Alo, Bhi);
                mma16(C[nt], Ahi, Blo);
                mma16(C[nt], Ahi, Bhi);
            }
        }

        // ---- layer 2 epilogue ----
        float p0 = 0.f, p1 = 0.f;
        #pragma unroll
        for (int nt = 0; nt < 8; nt++) {
            const int c0 = nh * 64 + nt * 8 + q * 2;
            const float bb0 = b1s[c0], bb1 = b1s[c0 + 1];
            const float ww0 = w2s[c0], ww1 = w2s[c0 + 1];
            p0 += tanhf(C[nt][0] + bb0) * ww0 + tanhf(C[nt][1] + bb1) * ww1;
            p1 += tanhf(C[nt][2] + bb0) * ww0 + tanhf(C[nt][3] + bb1) * ww1;
        }
        p0 += __shfl_xor_sync(0xffffffffu, p0, 1);
        p0 += __shfl_xor_sync(0xffffffffu, p0, 2);
        p1 += __shfl_xor_sync(0xffffffffu, p1, 1);
        p1 += __shfl_xor_sync(0xffffffffu, p1, 2);
        if (q == 0) {
            red[(mt * 16 + r0)     * 2 + nh] = p0;
            red[(mt * 16 + r0 + 8) * 2 + nh] = p1;
        }
        __syncthreads();

        if (t < MTILE) {
            int ng = base + t;
            if (ng < NODES) {
                float s = red[t * 2] + red[t * 2 + 1] + b2v;
                if (SQUARE) {
                    g_gsq[ng] = s * s;
                    g_msg[ng] = 0.0f;   // fused zero for the edge pass
                } else {
                    out[ng] = s;
                }
            }
        }
        __syncthreads();
    }
}

// ---------------------------------------------------------------------------
// Edge pass: msg[dst] += W[e] * gsq[src]
// ---------------------------------------------------------------------------
__global__ void edge_kernel(const int* __restrict__ src,
                            const int* __restrict__ dst,
                            const float* __restrict__ W,
                            int n_edges)
{
    int i = blockIdx.x * blockDim.x + threadIdx.x;
    if (i < n_edges) {
        const float m = W[i] * g_gsq[src[i]];
        atomicAdd(&g_msg[dst[i]], m);
    }
}

// ---------------------------------------------------------------------------
extern "C" void kernel_launch(void* const* d_in, const int* in_sizes, int n_in,
                              void* d_out, int out_size)
{
    const float* v    = (const float*)d_in[0];
    const float* exc  = (const float*)d_in[1];
    const int*   esrc = (const int*)  d_in[2];
    const int*   edst = (const int*)  d_in[3];
    const float* a    = (const float*)d_in[4];
    const float* W    = (const float*)d_in[5];
    const float* g0w  = (const float*)d_in[6];
    const float* g0b  = (const float*)d_in[7];
    const float* g1w  = (const float*)d_in[8];
    const float* g1b  = (const float*)d_in[9];
    const float* g2w  = (const float*)d_in[10];
    const float* g2b  = (const float*)d_in[11];
    const float* f0w  = (const float*)d_in[12];
    const float* f0b  = (const float*)d_in[13];
    const float* f1w  = (const float*)d_in[14];
    const float* f1b  = (const float*)d_in[15];
    const float* f2w  = (const float*)d_in[16];
    const float* f2b  = (const float*)d_in[17];
    float*       out  = (float*)d_out;

    const int n_edges = in_sizes[2];

    const int smem_bytes =
        (HID * W_S2U + MTILE * H_S2U) * 8 +
        (MTILE * 5 + 5 * HID + 3 * HID + MTILE * 2) * 4;   // ~147 KB

    cudaFuncSetAttribute(mlp_mma_kernel<3, true>,
                         cudaFuncAttributeMaxDynamicSharedMemorySize, smem_bytes);
    cudaFuncSetAttribute(mlp_mma_kernel<5, false>,
                         cudaFuncAttributeMaxDynamicSharedMemorySize, smem_bytes);

    mlp_mma_kernel<3, true><<<GRID, THREADS, smem_bytes>>>(
        v, a, nullptr, g0w, g0b, g1w, g1b, g2w, g2b, nullptr);

    edge_kernel<<<(n_edges + 255) / 256, 256>>>(esrc, edst, W, n_edges);

    mlp_mma_kernel<5, false><<<GRID, THREADS, smem_bytes>>>(
        v, a, exc, f0w, f0b, f1w, f1b, f2w, f2b, out);
}

// round 7
// speedup vs baseline: 2.2543x; 1.0030x over previous
#include <cuda_runtime.h>
#include <cuda_bf16.h>
#include <math.h>
#include <stdint.h>

#define NODES   50000
#define HID     128
#define MTILE   128
#define NTILES  ((NODES + MTILE - 1) / MTILE)   // 391
#define THREADS 512
#define GRID    148

// plane strides in uint2 units: ==4 (mod 16) -> conflict-free LDS.64
#define H_S2U 68
#define W_S2U 68

// Scratch (allocation-free rule: __device__ globals)
__device__ float g_gsq[NODES];
__device__ float g_msg[NODES];

// ---------------------------------------------------------------------------
// Branch-free hardware tanh: 2 MUFU + 4 ALU/FMA, abs err ~4e-7.
//   t = clamp(2*log2(e)*x, +-30); e = 2^t; tanh = (e-1)/(e+1)
// ---------------------------------------------------------------------------
__device__ __forceinline__ float fast_tanh(float x) {
    float t = fminf(fmaxf(x * 2.885390082f, -30.0f), 30.0f);
    float e;
    asm("ex2.approx.f32 %0, %1;" : "=f"(e) : "f"(t));
    float r;
    asm("rcp.approx.f32 %0, %1;" : "=f"(r) : "f"(e + 1.0f));
    return (e - 1.0f) * r;
}

// ---------------------------------------------------------------------------
// bf16x3 helpers: x ~ hi + lo (bf16 each). A*B ~= Ahi*Bhi + Ahi*Blo + Alo*Bhi
// ---------------------------------------------------------------------------
__device__ __forceinline__ float bfround(float x) {
    return __bfloat162float(__float2bfloat16(x));
}
// pack two floats as bf16x2; f_even -> low 16 bits (k even), f_odd -> high
__device__ __forceinline__ uint32_t bfpack(float f_even, float f_odd) {
    uint32_t r;
    asm("cvt.rn.bf16x2.f32 %0, %1, %2;" : "=r"(r) : "f"(f_odd), "f"(f_even));
    return r;
}
__device__ __forceinline__ void mma16(float* c, const uint32_t* a, const uint32_t* b) {
    asm volatile(
        "mma.sync.aligned.m16n8k16.row.col.f32.bf16.bf16.f32 "
        "{%0,%1,%2,%3}, {%4,%5,%6,%7}, {%8,%9}, {%0,%1,%2,%3};"
        : "+f"(c[0]), "+f"(c[1]), "+f"(c[2]), "+f"(c[3])
        : "r"(a[0]), "r"(a[1]), "r"(a[2]), "r"(a[3]),
          "r"(b[0]), "r"(b[1]));
}

// ---------------------------------------------------------------------------
// Persistent fused 3-layer MLP (bf16x3 tensor-core middle layer).
// ---------------------------------------------------------------------------
template <int IN_DIM, bool SQUARE>
__global__ void __launch_bounds__(THREADS, 1) mlp_mma_kernel(
    const float* __restrict__ v,
    const float* __restrict__ a,
    const float* __restrict__ exc,
    const float* __restrict__ w0, const float* __restrict__ b0,
    const float* __restrict__ w1, const float* __restrict__ b1,
    const float* __restrict__ w2, const float* __restrict__ b2,
    float* __restrict__ out)
{
    extern __shared__ float sm[];
    uint2* Wt2 = (uint2*)sm;                       // HID * W_S2U uint2
    uint2* Hs2 = Wt2 + HID * W_S2U;                // MTILE * H_S2U
    float* xs  = (float*)(Hs2 + MTILE * H_S2U);    // MTILE * IN_DIM
    float* w0s = xs + MTILE * 5;                   // IN_DIM * HID
    float* b0s = w0s + 5 * HID;
    float* b1s = b0s + HID;
    float* w2s = b1s + HID;
    float* red = w2s + HID;                        // MTILE * 2

    const int t    = threadIdx.x;
    const int wrp  = t >> 5, lane = t & 31;
    const int mt   = wrp & 7, nh = wrp >> 3;
    const int r0   = lane >> 2, q = lane & 3;

    // ---- one-time staging: W1^T split into bf16 hi/lo planes ----
    for (int i = t; i < HID * HID / 2; i += THREADS) {
        int j = i >> 7;          // kpair 0..63
        int n = i & 127;         // output col
        float e  = w1[(2 * j)     * HID + n];
        float o  = w1[(2 * j + 1) * HID + n];
        float eh = bfround(e), oh = bfround(o);
        Wt2[n * W_S2U + j] = make_uint2(bfpack(eh, oh),
                                        bfpack(e - eh, o - oh));
    }
    for (int i = t; i < IN_DIM * HID; i += THREADS) w0s[i] = w0[i];
    if (t < HID) { b0s[t] = b0[t]; b1s[t] = b1[t]; w2s[t] = w2[t]; }
    const float b2v = b2[0];
    __syncthreads();

    for (int tile = blockIdx.x; tile < NTILES; tile += GRID) {
        const int base = tile * MTILE;

        // ---- load node inputs ----
        if (t < MTILE) {
            int ng = base + t;
            bool ok = ng < NODES;
            xs[t * IN_DIM + 0] = ok ? v[ng]         : 0.0f;
            xs[t * IN_DIM + 1] = ok ? a[2 * ng]     : 0.0f;
            xs[t * IN_DIM + 2] = ok ? a[2 * ng + 1] : 0.0f;
            if (IN_DIM == 5) {
                xs[t * IN_DIM + 3] = ok ? g_msg[ng] : 0.0f;
                xs[t * IN_DIM + 4] = ok ? exc[ng]   : 0.0f;
            }
        }
        __syncthreads();

        // ---- layer 0: H0 = tanh(x @ w0 + b0), split+pack to bf16 planes ----
        #pragma unroll 4
        for (int i = t; i < MTILE * HID / 2; i += THREADS) {
            int node = i >> 6, j = i & 63;
            const float* x = &xs[node * IN_DIM];
            float acc0 = b0s[2 * j], acc1 = b0s[2 * j + 1];
            #pragma unroll
            for (int d = 0; d < IN_DIM; d++) {
                acc0 += x[d] * w0s[d * HID + 2 * j];
                acc1 += x[d] * w0s[d * HID + 2 * j + 1];
            }
            float h0 = fast_tanh(acc0), h1 = fast_tanh(acc1);
            float h0h = bfround(h0), h1h = bfround(h1);
            Hs2[node * H_S2U + j] = make_uint2(bfpack(h0h, h1h),
                                               bfpack(h0 - h0h, h1 - h1h));
        }
        __syncthreads();

        // ---- layer 1: 128x128x128 GEMM tile, bf16x3, pure LDS+MMA ----
        float C[8][4];
        #pragma unroll
        for (int i = 0; i < 8; i++) {
            C[i][0] = 0.f; C[i][1] = 0.f; C[i][2] = 0.f; C[i][3] = 0.f;
        }

        const uint2* Arow0 = &Hs2[(mt * 16 + r0) * H_S2U];
        const uint2* Arow1 = Arow0 + 8 * H_S2U;

        #pragma unroll
        for (int ks = 0; ks < 8; ks++) {            // K = 8 * 16
            const int jb = ks * 8;
            uint2 a0 = Arow0[jb + q];
            uint2 a1 = Arow1[jb + q];
            uint2 a2 = Arow0[jb + q + 4];
            uint2 a3 = Arow1[jb + q + 4];
            uint32_t Ahi[4] = {a0.x, a1.x, a2.x, a3.x};
            uint32_t Alo[4] = {a0.y, a1.y, a2.y, a3.y};
            #pragma unroll
            for (int nt = 0; nt < 8; nt++) {
                const uint2* Bp = &Wt2[(nh * 64 + nt * 8 + r0) * W_S2U + jb];
                uint2 b0v = Bp[q];
                uint2 b1v = Bp[q + 4];
                uint32_t Bhi[2] = {b0v.x, b1v.x};
                uint32_t Blo[2] = {b0v.y, b1v.y};
                mma16(C[nt], Alo, Bhi);
                mma16(C[nt], Ahi, Blo);
                mma16(C[nt], Ahi, Bhi);
            }
        }

        // ---- layer 2 epilogue ----
        float p0 = 0.f, p1 = 0.f;
        #pragma unroll
        for (int nt = 0; nt < 8; nt++) {
            const int c0 = nh * 64 + nt * 8 + q * 2;
            const float bb0 = b1s[c0], bb1 = b1s[c0 + 1];
            const float ww0 = w2s[c0], ww1 = w2s[c0 + 1];
            p0 += fast_tanh(C[nt][0] + bb0) * ww0 + fast_tanh(C[nt][1] + bb1) * ww1;
            p1 += fast_tanh(C[nt][2] + bb0) * ww0 + fast_tanh(C[nt][3] + bb1) * ww1;
        }
        p0 += __shfl_xor_sync(0xffffffffu, p0, 1);
        p0 += __shfl_xor_sync(0xffffffffu, p0, 2);
        p1 += __shfl_xor_sync(0xffffffffu, p1, 1);
        p1 += __shfl_xor_sync(0xffffffffu, p1, 2);
        if (q == 0) {
            red[(mt * 16 + r0)     * 2 + nh] = p0;
            red[(mt * 16 + r0 + 8) * 2 + nh] = p1;
        }
        __syncthreads();

        if (t < MTILE) {
            int ng = base + t;
            if (ng < NODES) {
                float s = red[t * 2] + red[t * 2 + 1] + b2v;
                if (SQUARE) {
                    g_gsq[ng] = s * s;
                    g_msg[ng] = 0.0f;   // fused zero for the edge pass
                } else {
                    out[ng] = s;
                }
            }
        }
        __syncthreads();
    }
}

// ---------------------------------------------------------------------------
// Edge pass: msg[dst] += W[e] * gsq[src]
// ---------------------------------------------------------------------------
__global__ void edge_kernel(const int* __restrict__ src,
                            const int* __restrict__ dst,
                            const float* __restrict__ W,
                            int n_edges)
{
    int i = blockIdx.x * blockDim.x + threadIdx.x;
    if (i < n_edges) {
        const float m = W[i] * g_gsq[src[i]];
        atomicAdd(&g_msg[dst[i]], m);
    }
}

// ---------------------------------------------------------------------------
extern "C" void kernel_launch(void* const* d_in, const int* in_sizes, int n_in,
                              void* d_out, int out_size)
{
    const float* v    = (const float*)d_in[0];
    const float* exc  = (const float*)d_in[1];
    const int*   esrc = (const int*)  d_in[2];
    const int*   edst = (const int*)  d_in[3];
    const float* a    = (const float*)d_in[4];
    const float* W    = (const float*)d_in[5];
    const float* g0w  = (const float*)d_in[6];
    const float* g0b  = (const float*)d_in[7];
    const float* g1w  = (const float*)d_in[8];
    const float* g1b  = (const float*)d_in[9];
    const float* g2w  = (const float*)d_in[10];
    const float* g2b  = (const float*)d_in[11];
    const float* f0w  = (const float*)d_in[12];
    const float* f0b  = (const float*)d_in[13];
    const float* f1w  = (const float*)d_in[14];
    const float* f1b  = (const float*)d_in[15];
    const float* f2w  = (const float*)d_in[16];
    const float* f2b  = (const float*)d_in[17];
    float*       out  = (float*)d_out;

    const int n_edges = in_sizes[2];

    const int smem_bytes =
        (HID * W_S2U + MTILE * H_S2U) * 8 +
        (MTILE * 5 + 5 * HID + 3 * HID + MTILE * 2) * 4;   // ~147 KB

    cudaFuncSetAttribute(mlp_mma_kernel<3, true>,
                         cudaFuncAttributeMaxDynamicSharedMemorySize, smem_bytes);
    cudaFuncSetAttribute(mlp_mma_kernel<5, false>,
                         cudaFuncAttributeMaxDynamicSharedMemorySize, smem_bytes);

    mlp_mma_kernel<3, true><<<GRID, THREADS, smem_bytes>>>(
        v, a, nullptr, g0w, g0b, g1w, g1b, g2w, g2b, nullptr);

    edge_kernel<<<(n_edges + 255) / 256, 256>>>(esrc, edst, W, n_edges);

    mlp_mma_kernel<5, false><<<GRID, THREADS, smem_bytes>>>(
        v, a, exc, f0w, f0b, f1w, f1b, f2w, f2b, out);
}

// round 8
// speedup vs baseline: 2.3112x; 1.0253x over previous
#include <cuda_runtime.h>
#include <cuda_bf16.h>
#include <math.h>
#include <stdint.h>

#define NODES   50000
#define HID     128
#define MTILE   128
#define NTILES  ((NODES + MTILE - 1) / MTILE)   // 391
#define THREADS 1024
#define GRID    148

// plane strides in uint2 units: ==4 (mod 16) / injective per 16-lane phase
#define H_S2U  68    // Hs2: layer-0 output, row-major (node x kpair)
#define W_S2U  68    // Wt2: layer-1 weights, n-major (col x kpair)
#define X_S2U  12    // Xs2: inputs, row-major (node x kpair), K=16 padded
#define W0_S2U 12    // Wt0: layer-0 weights, n-major (col x kpair)

// Scratch (allocation-free rule: __device__ globals)
__device__ float g_gsq[NODES];
__device__ float g_msg[NODES];

// ---------------------------------------------------------------------------
// Branch-free hardware tanh: t = clamp(2*log2e*x); e=2^t; (e-1)/(e+1)
// ---------------------------------------------------------------------------
__device__ __forceinline__ float fast_tanh(float x) {
    float t = fminf(fmaxf(x * 2.885390082f, -30.0f), 30.0f);
    float e;
    asm("ex2.approx.f32 %0, %1;" : "=f"(e) : "f"(t));
    float r;
    asm("rcp.approx.f32 %0, %1;" : "=f"(r) : "f"(e + 1.0f));
    return (e - 1.0f) * r;
}

// ---------------------------------------------------------------------------
// bf16x3 helpers: x ~ hi + lo. A*B ~= Ahi*Bhi + Ahi*Blo + Alo*Bhi
// ---------------------------------------------------------------------------
__device__ __forceinline__ float bfround(float x) {
    return __bfloat162float(__float2bfloat16(x));
}
__device__ __forceinline__ uint32_t bfpack(float f_even, float f_odd) {
    uint32_t r;
    asm("cvt.rn.bf16x2.f32 %0, %1, %2;" : "=r"(r) : "f"(f_odd), "f"(f_even));
    return r;
}
__device__ __forceinline__ uint2 split2(float e, float o) {
    float eh = bfround(e), oh = bfround(o);
    return make_uint2(bfpack(eh, oh), bfpack(e - eh, o - oh));
}
__device__ __forceinline__ void mma16(float* c, const uint32_t* a, const uint32_t* b) {
    asm volatile(
        "mma.sync.aligned.m16n8k16.row.col.f32.bf16.bf16.f32 "
        "{%0,%1,%2,%3}, {%4,%5,%6,%7}, {%8,%9}, {%0,%1,%2,%3};"
        : "+f"(c[0]), "+f"(c[1]), "+f"(c[2]), "+f"(c[3])
        : "r"(a[0]), "r"(a[1]), "r"(a[2]), "r"(a[3]),
          "r"(b[0]), "r"(b[1]));
}

// ---------------------------------------------------------------------------
// Persistent fused 3-layer MLP, all-MMA (bf16x3).
// 32 warps: mt = wrp&7 -> 16-row m-tile, nq = wrp>>3 -> 32-col n-quarter.
// ---------------------------------------------------------------------------
template <int IN_DIM, bool SQUARE>
__global__ void __launch_bounds__(THREADS, 1) mlp_mma_kernel(
    const float* __restrict__ v,
    const float* __restrict__ a,
    const float* __restrict__ exc,
    const float* __restrict__ w0, const float* __restrict__ b0,
    const float* __restrict__ w1, const float* __restrict__ b1,
    const float* __restrict__ w2, const float* __restrict__ b2,
    float* __restrict__ out)
{
    extern __shared__ float sm[];
    uint2* Wt2 = (uint2*)sm;                       // HID * 68 uint2   (69.6 KB)
    uint2* Hs2 = Wt2 + HID * W_S2U;                // MTILE * 68       (69.6 KB)
    uint2* Xs2 = Hs2 + MTILE * H_S2U;              // MTILE * 12       (12 KB)
    uint2* Wt0 = Xs2 + MTILE * X_S2U;              // HID * 12         (12 KB)
    float* b0s = (float*)(Wt0 + HID * W0_S2U);     // HID
    float* b1s = b0s + HID;                        // HID
    float* w2s = b1s + HID;                        // HID
    float* red = w2s + HID;                        // MTILE * 4

    const int t    = threadIdx.x;
    const int wrp  = t >> 5, lane = t & 31;
    const int mt   = wrp & 7, nq = wrp >> 3;
    const int r0   = lane >> 2, q = lane & 3;

    // ---- one-time staging ----
    // W1^T -> bf16 hi/lo planes (n-major)
    for (int i = t; i < HID * HID / 2; i += THREADS) {
        int j = i >> 7;          // kpair 0..63
        int n = i & 127;         // output col
        Wt2[n * W_S2U + j] = split2(w1[(2 * j) * HID + n],
                                    w1[(2 * j + 1) * HID + n]);
    }
    // W0^T (K padded 5->16) -> bf16 hi/lo (n-major); one entry per thread
    {
        int n = t & 127, j = t >> 7;  // j 0..7
        float e = (2 * j     < IN_DIM) ? w0[(2 * j)     * HID + n] : 0.0f;
        float o = (2 * j + 1 < IN_DIM) ? w0[(2 * j + 1) * HID + n] : 0.0f;
        Wt0[n * W0_S2U + j] = split2(e, o);
    }
    if (t < HID) { b0s[t] = b0[t]; b1s[t] = b1[t]; w2s[t] = w2[t]; }
    const float b2v = b2[0];
    __syncthreads();

    for (int tile = blockIdx.x; tile < NTILES; tile += GRID) {
        const int base = tile * MTILE;

        // ---- stage node inputs, pre-split into Xs2 (K=16, 5 used) ----
        if (t < MTILE) {
            int ng = base + t;
            bool ok = ng < NODES;
            float x[5];
            x[0] = ok ? v[ng]         : 0.0f;
            x[1] = ok ? a[2 * ng]     : 0.0f;
            x[2] = ok ? a[2 * ng + 1] : 0.0f;
            x[3] = (IN_DIM == 5 && ok) ? g_msg[ng] : 0.0f;
            x[4] = (IN_DIM == 5 && ok) ? exc[ng]   : 0.0f;
            uint2* X = &Xs2[t * X_S2U];
            #pragma unroll
            for (int j = 0; j < 8; j++) {
                float e = (2 * j     < 5) ? x[2 * j]     : 0.0f;
                float o = (2 * j + 1 < 5) ? x[2 * j + 1] : 0.0f;
                X[j] = split2(e, o);
            }
        }
        __syncthreads();

        // ---- layer 0 as MMA: H0 = tanh(x @ w0 + b0) ----
        {
            float C0[4][4];
            #pragma unroll
            for (int i = 0; i < 4; i++) {
                C0[i][0] = 0.f; C0[i][1] = 0.f; C0[i][2] = 0.f; C0[i][3] = 0.f;
            }
            const uint2* X0 = &Xs2[(mt * 16 + r0) * X_S2U];
            const uint2* X1 = X0 + 8 * X_S2U;
            uint2 a0 = X0[q], a1 = X1[q], a2 = X0[q + 4], a3 = X1[q + 4];
            uint32_t Ahi[4] = {a0.x, a1.x, a2.x, a3.x};
            uint32_t Alo[4] = {a0.y, a1.y, a2.y, a3.y};
            #pragma unroll
            for (int nt = 0; nt < 4; nt++) {
                const uint2* Bp = &Wt0[(nq * 32 + nt * 8 + r0) * W0_S2U];
                uint2 b0v = Bp[q], b1v = Bp[q + 4];
                uint32_t Bhi[2] = {b0v.x, b1v.x};
                uint32_t Blo[2] = {b0v.y, b1v.y};
                mma16(C0[nt], Alo, Bhi);
                mma16(C0[nt], Ahi, Blo);
                mma16(C0[nt], Ahi, Bhi);
            }
            // tanh + bias, split, store into Hs2 (cols 2q,2q+1 = one kpair)
            #pragma unroll
            for (int nt = 0; nt < 4; nt++) {
                const int col0 = nq * 32 + nt * 8 + q * 2;
                const float bb0 = b0s[col0], bb1 = b0s[col0 + 1];
                float h00 = fast_tanh(C0[nt][0] + bb0);
                float h01 = fast_tanh(C0[nt][1] + bb1);
                float h10 = fast_tanh(C0[nt][2] + bb0);
                float h11 = fast_tanh(C0[nt][3] + bb1);
                const int jp = nq * 16 + nt * 4 + q;
                Hs2[(mt * 16 + r0)     * H_S2U + jp] = split2(h00, h01);
                Hs2[(mt * 16 + r0 + 8) * H_S2U + jp] = split2(h10, h11);
            }
        }
        __syncthreads();

        // ---- layer 1: 128x128x128 GEMM tile, bf16x3, pure LDS+MMA ----
        float C[4][4];
        #pragma unroll
        for (int i = 0; i < 4; i++) {
            C[i][0] = 0.f; C[i][1] = 0.f; C[i][2] = 0.f; C[i][3] = 0.f;
        }
        const uint2* Arow0 = &Hs2[(mt * 16 + r0) * H_S2U];
        const uint2* Arow1 = Arow0 + 8 * H_S2U;

        #pragma unroll
        for (int ks = 0; ks < 8; ks++) {            // K = 8 * 16
            const int jb = ks * 8;
            uint2 a0 = Arow0[jb + q];
            uint2 a1 = Arow1[jb + q];
            uint2 a2 = Arow0[jb + q + 4];
            uint2 a3 = Arow1[jb + q + 4];
            uint32_t Ahi[4] = {a0.x, a1.x, a2.x, a3.x};
            uint32_t Alo[4] = {a0.y, a1.y, a2.y, a3.y};
            #pragma unroll
            for (int nt = 0; nt < 4; nt++) {
                const uint2* Bp = &Wt2[(nq * 32 + nt * 8 + r0) * W_S2U + jb];
                uint2 b0v = Bp[q];
                uint2 b1v = Bp[q + 4];
                uint32_t Bhi[2] = {b0v.x, b1v.x};
                uint32_t Blo[2] = {b0v.y, b1v.y};
                mma16(C[nt], Alo, Bhi);
                mma16(C[nt], Ahi, Blo);
                mma16(C[nt], Ahi, Bhi);
            }
        }

        // ---- layer 2 epilogue: out = sum_c tanh(C+b1)[c] * w2[c] + b2 ----
        float p0 = 0.f, p1 = 0.f;
        #pragma unroll
        for (int nt = 0; nt < 4; nt++) {
            const int c0 = nq * 32 + nt * 8 + q * 2;
            const float bb0 = b1s[c0], bb1 = b1s[c0 + 1];
            const float ww0 = w2s[c0], ww1 = w2s[c0 + 1];
            p0 += fast_tanh(C[nt][0] + bb0) * ww0 + fast_tanh(C[nt][1] + bb1) * ww1;
            p1 += fast_tanh(C[nt][2] + bb0) * ww0 + fast_tanh(C[nt][3] + bb1) * ww1;
        }
        p0 += __shfl_xor_sync(0xffffffffu, p0, 1);
        p0 += __shfl_xor_sync(0xffffffffu, p0, 2);
        p1 += __shfl_xor_sync(0xffffffffu, p1, 1);
        p1 += __shfl_xor_sync(0xffffffffu, p1, 2);
        if (q == 0) {
            red[(mt * 16 + r0)     * 4 + nq] = p0;
            red[(mt * 16 + r0 + 8) * 4 + nq] = p1;
        }
        __syncthreads();

        if (t < MTILE) {
            int ng = base + t;
            if (ng < NODES) {
                float s = red[t * 4] + red[t * 4 + 1] +
                          red[t * 4 + 2] + red[t * 4 + 3] + b2v;
                if (SQUARE) {
                    g_gsq[ng] = s * s;
                    g_msg[ng] = 0.0f;   // fused zero for the edge pass
                } else {
                    out[ng] = s;
                }
            }
        }
        __syncthreads();
    }
}

// ---------------------------------------------------------------------------
// Edge pass: msg[dst] += W[e] * gsq[src]
// ---------------------------------------------------------------------------
__global__ void edge_kernel(const int* __restrict__ src,
                            const int* __restrict__ dst,
                            const float* __restrict__ W,
                            int n_edges)
{
    int i = blockIdx.x * blockDim.x + threadIdx.x;
    if (i < n_edges) {
        const float m = W[i] * g_gsq[src[i]];
        atomicAdd(&g_msg[dst[i]], m);
    }
}

// ---------------------------------------------------------------------------
extern "C" void kernel_launch(void* const* d_in, const int* in_sizes, int n_in,
                              void* d_out, int out_size)
{
    const float* v    = (const float*)d_in[0];
    const float* exc  = (const float*)d_in[1];
    const int*   esrc = (const int*)  d_in[2];
    const int*   edst = (const int*)  d_in[3];
    const float* a    = (const float*)d_in[4];
    const float* W    = (const float*)d_in[5];
    const float* g0w  = (const float*)d_in[6];
    const float* g0b  = (const float*)d_in[7];
    const float* g1w  = (const float*)d_in[8];
    const float* g1b  = (const float*)d_in[9];
    const float* g2w  = (const float*)d_in[10];
    const float* g2b  = (const float*)d_in[11];
    const float* f0w  = (const float*)d_in[12];
    const float* f0b  = (const float*)d_in[13];
    const float* f1w  = (const float*)d_in[14];
    const float* f1b  = (const float*)d_in[15];
    const float* f2w  = (const float*)d_in[16];
    const float* f2b  = (const float*)d_in[17];
    float*       out  = (float*)d_out;

    const int n_edges = in_sizes[2];

    const int smem_bytes =
        (HID * W_S2U + MTILE * H_S2U + MTILE * X_S2U + HID * W0_S2U) * 8 +
        (3 * HID + MTILE * 4) * 4;   // ~164 KB

    cudaFuncSetAttribute(mlp_mma_kernel<3, true>,
                         cudaFuncAttributeMaxDynamicSharedMemorySize, smem_bytes);
    cudaFuncSetAttribute(mlp_mma_kernel<5, false>,
                         cudaFuncAttributeMaxDynamicSharedMemorySize, smem_bytes);

    mlp_mma_kernel<3, true><<<GRID, THREADS, smem_bytes>>>(
        v, a, nullptr, g0w, g0b, g1w, g1b, g2w, g2b, nullptr);

    edge_kernel<<<(n_edges + 255) / 256, 256>>>(esrc, edst, W, n_edges);

    mlp_mma_kernel<5, false><<<GRID, THREADS, smem_bytes>>>(
        v, a, exc, f0w, f0b, f1w, f1b, f2w, f2b, out);
}

// round 10
// speedup vs baseline: 2.5753x; 1.1143x over previous
#include <cuda_runtime.h>
#include <cuda_bf16.h>
#include <math.h>
#include <stdint.h>

#define NODES   50000
#define HID     128
#define MTILE   128
#define NTILES  ((NODES + MTILE - 1) / MTILE)   // 391
#define THREADS 1024
#define GRID    148

// Does this device compilation expose tcgen05 (arch-specific sm_103a/sm_100a)?
#if defined(__CUDA_ARCH__) && \
    (defined(__CUDA_ARCH_FEAT_SM103_ALL) || defined(__CUDA_ARCH_FEAT_SM100_ALL))
#define TC_PATH 1
#else
#define TC_PATH 0
#endif

// ---- fallback (mma.sync) smem plane strides, uint2 units ----
#define H_S2U  68
#define W_S2U  68
#define X_S2U  12
#define W0_S2U 12

// ---- tcgen05 smem layout (byte offsets from 1024-aligned base) ----
#define PLANE_BYTES 32768                      // 128 x 128 bf16 blocked SW128
#define AHI_OFF  0
#define ALO_OFF  (PLANE_BYTES)
#define BHI_OFF  (2 * PLANE_BYTES)
#define BLO_OFF  (3 * PLANE_BYTES)
#define XS_OFF   (4 * PLANE_BYTES)
#define W0S_OFF  (XS_OFF  + MTILE * 5 * 4)
#define B0S_OFF  (W0S_OFF + 5 * HID * 4)
#define B1S_OFF  (B0S_OFF + HID * 4)
#define W2S_OFF  (B1S_OFF + HID * 4)
#define RED_OFF  (W2S_OFF + HID * 4)
#define PTR_OFF  (RED_OFF + MTILE * 4 * 4)
#define MBAR_OFF (PTR_OFF + 16)
#define TC_SMEM  (MBAR_OFF + 16 + 1024)        // + alignment slack

#define MMA_SMEM ((HID * W_S2U + MTILE * H_S2U + MTILE * X_S2U + HID * W0_S2U) * 8 + \
                  (3 * HID + MTILE * 4) * 4)
#define SMEM_BYTES (TC_SMEM > MMA_SMEM ? TC_SMEM : MMA_SMEM)

#define TMEM_COLS 512
// idesc kind::f16: F32 accum, bf16 x bf16, N=128, M=128
#define MMA_IDESC 0x8200490u

// Scratch (allocation-free rule: __device__ globals)
__device__ float g_gsq[NODES];
__device__ float g_msg[NODES];

// ---------------------------------------------------------------------------
// shared helpers
// ---------------------------------------------------------------------------
__device__ __forceinline__ float fast_tanh(float x) {
    float t = fminf(fmaxf(x * 2.885390082f, -30.0f), 30.0f);
    float e;
    asm("ex2.approx.f32 %0, %1;" : "=f"(e) : "f"(t));
    float r;
    asm("rcp.approx.f32 %0, %1;" : "=f"(r) : "f"(e + 1.0f));
    return (e - 1.0f) * r;
}
__device__ __forceinline__ float bfround(float x) {
    return __bfloat162float(__float2bfloat16(x));
}
__device__ __forceinline__ uint32_t bfpack(float f_even, float f_odd) {
    uint32_t r;
    asm("cvt.rn.bf16x2.f32 %0, %1, %2;" : "=r"(r) : "f"(f_odd), "f"(f_even));
    return r;
}
__device__ __forceinline__ uint2 split2(float e, float o) {
    float eh = bfround(e), oh = bfround(o);
    return make_uint2(bfpack(eh, oh), bfpack(e - eh, o - oh));
}
__device__ __forceinline__ uint32_t smem_u32(const void* p) {
    uint32_t r;
    asm("{ .reg .u64 t; cvta.to.shared.u64 t, %1; cvt.u32.u64 %0, t; }"
        : "=r"(r) : "l"(p));
    return r;
}

#if TC_PATH
// ---------------------------------------------------------------------------
// tcgen05 helpers
// ---------------------------------------------------------------------------
// blocked SW128 byte offset for bf16 tile [128 rows x 128 cols]
// atom = 8 rows x 64 bf16 (1024B); atom_offset = (row>>3) + (col>>6)*16
__device__ __forceinline__ uint32_t blk_off(int row, int col) {
    uint32_t off = (uint32_t)(((row >> 3) + ((col >> 6) << 4)) << 10)
                 + ((row & 7) << 7) + ((col & 63) << 1);
    return off ^ ((off >> 3) & 0x70);
}
__device__ __forceinline__ uint64_t make_desc(uint32_t saddr) {
    return ((uint64_t)2 << 61) | ((uint64_t)1 << 46) |
           ((uint64_t)64 << 32) | ((uint64_t)1 << 16) |
           (((uint64_t)(saddr >> 4)) & 0x3FFF);
}
__device__ __forceinline__ void tc_mma_f16_ss(uint32_t d_tmem, uint64_t a_desc,
                                              uint64_t b_desc, uint32_t en) {
    asm volatile(
        "{\n\t"
        ".reg .pred p;\n\t"
        "setp.ne.u32 p, %4, 0;\n\t"
        "tcgen05.mma.cta_group::1.kind::f16 [%0], %1, %2, %3, "
        "{%5, %5, %5, %5}, p;\n\t"
        "}"
        :: "r"(d_tmem), "l"(a_desc), "l"(b_desc), "r"(MMA_IDESC),
           "r"(en), "r"(0u)
        : "memory");
}
__device__ __forceinline__ void mbar_wait(uint32_t mbar, uint32_t parity) {
    asm volatile(
        "{\n\t"
        ".reg .pred P;\n\t"
        "WAIT_%=:\n\t"
        "mbarrier.try_wait.parity.acquire.cta.shared::cta.b64 P, [%0], %1, 0x989680;\n\t"
        "@!P bra.uni WAIT_%=;\n\t"
        "}" :: "r"(mbar), "r"(parity) : "memory");
}
#else
// ---------------------------------------------------------------------------
// mma.sync helper (fallback)
// ---------------------------------------------------------------------------
__device__ __forceinline__ void mma16(float* c, const uint32_t* a, const uint32_t* b) {
    asm volatile(
        "mma.sync.aligned.m16n8k16.row.col.f32.bf16.bf16.f32 "
        "{%0,%1,%2,%3}, {%4,%5,%6,%7}, {%8,%9}, {%0,%1,%2,%3};"
        : "+f"(c[0]), "+f"(c[1]), "+f"(c[2]), "+f"(c[3])
        : "r"(a[0]), "r"(a[1]), "r"(a[2]), "r"(a[3]),
          "r"(b[0]), "r"(b[1]));
}
#endif

// ---------------------------------------------------------------------------
// Persistent fused 3-layer MLP (body chosen by TC_PATH)
// ---------------------------------------------------------------------------
template <int IN_DIM, bool SQUARE>
__global__ void __launch_bounds__(THREADS, 1) mlp_kernel(
    const float* __restrict__ v,
    const float* __restrict__ a,
    const float* __restrict__ exc,
    const float* __restrict__ w0, const float* __restrict__ b0,
    const float* __restrict__ w1, const float* __restrict__ b1,
    const float* __restrict__ w2, const float* __restrict__ b2,
    float* __restrict__ out)
{
#if TC_PATH
    // ======================= tcgen05 implementation ========================
    extern __shared__ char smraw[];
    const uint32_t raw32 = smem_u32(smraw);
    const uint32_t base  = (raw32 + 1023) & ~1023u;
    char* smb = smraw + (base - raw32);

    float* xs  = (float*)(smb + XS_OFF);
    float* w0s = (float*)(smb + W0S_OFF);
    float* b0s = (float*)(smb + B0S_OFF);
    float* b1s = (float*)(smb + B1S_OFF);
    float* w2s = (float*)(smb + W2S_OFF);
    float* red = (float*)(smb + RED_OFF);

    const int t   = threadIdx.x;
    const int wrp = t >> 5, lane = t & 31;

    if (wrp == 0) {
        asm volatile(
            "tcgen05.alloc.cta_group::1.sync.aligned.shared::cta.b32 [%0], %1;"
            :: "r"(base + PTR_OFF), "r"(TMEM_COLS) : "memory");
    }
    if (t == 0) {
        asm volatile("mbarrier.init.shared.b64 [%0], 1;"
                     :: "r"(base + MBAR_OFF) : "memory");
    }

    // stage once: W1^T -> Bhi/Blo planes; w0, biases
    for (int i = t; i < HID * HID / 2; i += THREADS) {
        int kp = i >> 7, n = i & 127;
        float e  = w1[(2 * kp)     * HID + n];
        float o  = w1[(2 * kp + 1) * HID + n];
        float eh = bfround(e), oh = bfround(o);
        uint32_t off = blk_off(n, 2 * kp);
        *(uint32_t*)(smb + BHI_OFF + off) = bfpack(eh, oh);
        *(uint32_t*)(smb + BLO_OFF + off) = bfpack(e - eh, o - oh);
    }
    for (int i = t; i < IN_DIM * HID; i += THREADS) w0s[i] = w0[i];
    if (t < HID) { b0s[t] = b0[t]; b1s[t] = b1[t]; w2s[t] = w2[t]; }
    const float b2v = b2[0];
    __syncthreads();

    uint32_t tmem_base;
    asm volatile("ld.shared.b32 %0, [%1];" : "=r"(tmem_base) : "r"(base + PTR_OFF));

    const uint64_t descAhi = make_desc(base + AHI_OFF);
    const uint64_t descAlo = make_desc(base + ALO_OFF);
    const uint64_t descBhi = make_desc(base + BHI_OFF);
    const uint64_t descBlo = make_desc(base + BLO_OFF);

    uint32_t parity = 0;

    for (int tile = blockIdx.x; tile < NTILES; tile += GRID) {
        const int tbase = tile * MTILE;

        if (t < MTILE) {
            int ng = tbase + t;
            bool ok = ng < NODES;
            xs[t * IN_DIM + 0] = ok ? v[ng]         : 0.0f;
            xs[t * IN_DIM + 1] = ok ? a[2 * ng]     : 0.0f;
            xs[t * IN_DIM + 2] = ok ? a[2 * ng + 1] : 0.0f;
            if (IN_DIM == 5) {
                xs[t * IN_DIM + 3] = ok ? g_msg[ng] : 0.0f;
                xs[t * IN_DIM + 4] = ok ? exc[ng]   : 0.0f;
            }
        }
        __syncthreads();

        // layer 0 scalar -> Ahi/Alo planes
        #pragma unroll
        for (int it = 0; it < MTILE * HID / 2 / THREADS; it++) {
            int i = it * THREADS + t;
            int node = i >> 6, jp = i & 63;
            const float* x = &xs[node * IN_DIM];
            float acc0 = b0s[2 * jp], acc1 = b0s[2 * jp + 1];
            #pragma unroll
            for (int d = 0; d < IN_DIM; d++) {
                acc0 += x[d] * w0s[d * HID + 2 * jp];
                acc1 += x[d] * w0s[d * HID + 2 * jp + 1];
            }
            float h0 = fast_tanh(acc0), h1 = fast_tanh(acc1);
            float h0h = bfround(h0), h1h = bfround(h1);
            uint32_t off = blk_off(node, 2 * jp);
            *(uint32_t*)(smb + AHI_OFF + off) = bfpack(h0h, h1h);
            *(uint32_t*)(smb + ALO_OFF + off) = bfpack(h0 - h0h, h1 - h1h);
        }
        __syncthreads();

        // layer 1: 24 tcgen05 dispatches (bf16x3, K=128)
        if (wrp == 0) {
            uint32_t one;
            asm volatile(
                "{\n\t.reg .pred p;\n\t"
                "elect.sync _|p, 0xFFFFFFFF;\n\t"
                "selp.b32 %0, 1, 0, p;\n\t}" : "=r"(one));
            if (one) {
                asm volatile("fence.proxy.async.shared::cta;" ::: "memory");
                #pragma unroll
                for (int ks = 0; ks < 8; ks++) {
                    uint64_t doff = (ks < 4) ? (uint64_t)(ks * 2)
                                             : (uint64_t)(1024 + (ks - 4) * 2);
                    tc_mma_f16_ss(tmem_base, descAlo + doff, descBhi + doff,
                                  ks > 0 ? 1u : 0u);
                    tc_mma_f16_ss(tmem_base, descAhi + doff, descBlo + doff, 1u);
                    tc_mma_f16_ss(tmem_base, descAhi + doff, descBhi + doff, 1u);
                }
                asm volatile(
                    "tcgen05.commit.cta_group::1.mbarrier::arrive::one.shared::cluster.b64 [%0];"
                    :: "r"(base + MBAR_OFF) : "memory");
            }
        }

        mbar_wait(base + MBAR_OFF, parity);
        parity ^= 1;
        asm volatile("tcgen05.fence::after_thread_sync;" ::: "memory");

        // epilogue: 16 warps read TMEM D, tanh-dot-reduce
        if (wrp < 16) {
            const int sub = wrp & 3;
            const int cg  = wrp >> 2;
            uint32_t dr[32];
            asm volatile(
                "tcgen05.ld.sync.aligned.32x32b.x32.b32 "
                "{%0,%1,%2,%3,%4,%5,%6,%7,%8,%9,%10,%11,%12,%13,%14,%15,"
                "%16,%17,%18,%19,%20,%21,%22,%23,%24,%25,%26,%27,%28,%29,%30,%31}, [%32];"
                : "=r"(dr[0]),  "=r"(dr[1]),  "=r"(dr[2]),  "=r"(dr[3]),
                  "=r"(dr[4]),  "=r"(dr[5]),  "=r"(dr[6]),  "=r"(dr[7]),
                  "=r"(dr[8]),  "=r"(dr[9]),  "=r"(dr[10]), "=r"(dr[11]),
                  "=r"(dr[12]), "=r"(dr[13]), "=r"(dr[14]), "=r"(dr[15]),
                  "=r"(dr[16]), "=r"(dr[17]), "=r"(dr[18]), "=r"(dr[19]),
                  "=r"(dr[20]), "=r"(dr[21]), "=r"(dr[22]), "=r"(dr[23]),
                  "=r"(dr[24]), "=r"(dr[25]), "=r"(dr[26]), "=r"(dr[27]),
                  "=r"(dr[28]), "=r"(dr[29]), "=r"(dr[30]), "=r"(dr[31])
                : "r"(tmem_base + cg * 32));
            asm volatile("tcgen05.wait::ld.sync.aligned;" ::: "memory");

            float p = 0.0f;
            #pragma unroll
            for (int c = 0; c < 32; c++) {
                int col = cg * 32 + c;
                p += fast_tanh(__uint_as_float(dr[c]) + b1s[col]) * w2s[col];
            }
            red[(sub * 32 + lane) * 4 + cg] = p;
            asm volatile("tcgen05.fence::before_thread_sync;" ::: "memory");
        }
        __syncthreads();

        if (t < MTILE) {
            int ng = tbase + t;
            if (ng < NODES) {
                float s = red[t * 4] + red[t * 4 + 1] +
                          red[t * 4 + 2] + red[t * 4 + 3] + b2v;
                if (SQUARE) { g_gsq[ng] = s * s; g_msg[ng] = 0.0f; }
                else        { out[ng] = s; }
            }
        }
        __syncthreads();
    }

    if (t == 0) {
        asm volatile("mbarrier.inval.shared.b64 [%0];"
                     :: "r"(base + MBAR_OFF) : "memory");
    }
    __syncthreads();
    if (wrp == 0) {
        asm volatile("tcgen05.relinquish_alloc_permit.cta_group::1.sync.aligned;");
        asm volatile("tcgen05.dealloc.cta_group::1.sync.aligned.b32 %0, %1;"
                     :: "r"(tmem_base), "r"(TMEM_COLS));
    }

#else
    // ================== fallback: round-8 mma.sync body ====================
    extern __shared__ float sm[];
    uint2* Wt2 = (uint2*)sm;
    uint2* Hs2 = Wt2 + HID * W_S2U;
    uint2* Xs2 = Hs2 + MTILE * H_S2U;
    uint2* Wt0 = Xs2 + MTILE * X_S2U;
    float* b0s = (float*)(Wt0 + HID * W0_S2U);
    float* b1s = b0s + HID;
    float* w2s = b1s + HID;
    float* red = w2s + HID;

    const int t    = threadIdx.x;
    const int wrp  = t >> 5, lane = t & 31;
    const int mt   = wrp & 7, nq = wrp >> 3;
    const int r0   = lane >> 2, q = lane & 3;

    for (int i = t; i < HID * HID / 2; i += THREADS) {
        int j = i >> 7, n = i & 127;
        Wt2[n * W_S2U + j] = split2(w1[(2 * j) * HID + n],
                                    w1[(2 * j + 1) * HID + n]);
    }
    {
        int n = t & 127, j = t >> 7;
        float e = (2 * j     < IN_DIM) ? w0[(2 * j)     * HID + n] : 0.0f;
        float o = (2 * j + 1 < IN_DIM) ? w0[(2 * j + 1) * HID + n] : 0.0f;
        Wt0[n * W0_S2U + j] = split2(e, o);
    }
    if (t < HID) { b0s[t] = b0[t]; b1s[t] = b1[t]; w2s[t] = w2[t]; }
    const float b2v = b2[0];
    __syncthreads();

    for (int tile = blockIdx.x; tile < NTILES; tile += GRID) {
        const int base = tile * MTILE;

        if (t < MTILE) {
            int ng = base + t;
            bool ok = ng < NODES;
            float x[5];
            x[0] = ok ? v[ng]         : 0.0f;
            x[1] = ok ? a[2 * ng]     : 0.0f;
            x[2] = ok ? a[2 * ng + 1] : 0.0f;
            x[3] = (IN_DIM == 5 && ok) ? g_msg[ng] : 0.0f;
            x[4] = (IN_DIM == 5 && ok) ? exc[ng]   : 0.0f;
            uint2* X = &Xs2[t * X_S2U];
            #pragma unroll
            for (int j = 0; j < 8; j++) {
                float e = (2 * j     < 5) ? x[2 * j]     : 0.0f;
                float o = (2 * j + 1 < 5) ? x[2 * j + 1] : 0.0f;
                X[j] = split2(e, o);
            }
        }
        __syncthreads();

        {
            float C0[4][4];
            #pragma unroll
            for (int i = 0; i < 4; i++) {
                C0[i][0] = 0.f; C0[i][1] = 0.f; C0[i][2] = 0.f; C0[i][3] = 0.f;
            }
            const uint2* X0 = &Xs2[(mt * 16 + r0) * X_S2U];
            const uint2* X1 = X0 + 8 * X_S2U;
            uint2 a0 = X0[q], a1 = X1[q], a2 = X0[q + 4], a3 = X1[q + 4];
            uint32_t Ahi[4] = {a0.x, a1.x, a2.x, a3.x};
            uint32_t Alo[4] = {a0.y, a1.y, a2.y, a3.y};
            #pragma unroll
            for (int nt = 0; nt < 4; nt++) {
                const uint2* Bp = &Wt0[(nq * 32 + nt * 8 + r0) * W0_S2U];
                uint2 b0v = Bp[q], b1v = Bp[q + 4];
                uint32_t Bhi[2] = {b0v.x, b1v.x};
                uint32_t Blo[2] = {b0v.y, b1v.y};
                mma16(C0[nt], Alo, Bhi);
                mma16(C0[nt], Ahi, Blo);
                mma16(C0[nt], Ahi, Bhi);
            }
            #pragma unroll
            for (int nt = 0; nt < 4; nt++) {
                const int col0 = nq * 32 + nt * 8 + q * 2;
                const float bb0 = b0s[col0], bb1 = b0s[col0 + 1];
                float h00 = fast_tanh(C0[nt][0] + bb0);
                float h01 = fast_tanh(C0[nt][1] + bb1);
                float h10 = fast_tanh(C0[nt][2] + bb0);
                float h11 = fast_tanh(C0[nt][3] + bb1);
                const int jp = nq * 16 + nt * 4 + q;
                Hs2[(mt * 16 + r0)     * H_S2U + jp] = split2(h00, h01);
                Hs2[(mt * 16 + r0 + 8) * H_S2U + jp] = split2(h10, h11);
            }
        }
        __syncthreads();

        float C[4][4];
        #pragma unroll
        for (int i = 0; i < 4; i++) {
            C[i][0] = 0.f; C[i][1] = 0.f; C[i][2] = 0.f; C[i][3] = 0.f;
        }
        const uint2* Arow0 = &Hs2[(mt * 16 + r0) * H_S2U];
        const uint2* Arow1 = Arow0 + 8 * H_S2U;

        #pragma unroll
        for (int ks = 0; ks < 8; ks++) {
            const int jb = ks * 8;
            uint2 a0 = Arow0[jb + q];
            uint2 a1 = Arow1[jb + q];
            uint2 a2 = Arow0[jb + q + 4];
            uint2 a3 = Arow1[jb + q + 4];
            uint32_t Ahi[4] = {a0.x, a1.x, a2.x, a3.x};
            uint32_t Alo[4] = {a0.y, a1.y, a2.y, a3.y};
            #pragma unroll
            for (int nt = 0; nt < 4; nt++) {
                const uint2* Bp = &Wt2[(nq * 32 + nt * 8 + r0) * W_S2U + jb];
                uint2 b0v = Bp[q];
                uint2 b1v = Bp[q + 4];
                uint32_t Bhi[2] = {b0v.x, b1v.x};
                uint32_t Blo[2] = {b0v.y, b1v.y};
                mma16(C[nt], Alo, Bhi);
                mma16(C[nt], Ahi, Blo);
                mma16(C[nt], Ahi, Bhi);
            }
        }

        float p0 = 0.f, p1 = 0.f;
        #pragma unroll
        for (int nt = 0; nt < 4; nt++) {
            const int c0 = nq * 32 + nt * 8 + q * 2;
            const float bb0 = b1s[c0], bb1 = b1s[c0 + 1];
            const float ww0 = w2s[c0], ww1 = w2s[c0 + 1];
            p0 += fast_tanh(C[nt][0] + bb0) * ww0 + fast_tanh(C[nt][1] + bb1) * ww1;
            p1 += fast_tanh(C[nt][2] + bb0) * ww0 + fast_tanh(C[nt][3] + bb1) * ww1;
        }
        p0 += __shfl_xor_sync(0xffffffffu, p0, 1);
        p0 += __shfl_xor_sync(0xffffffffu, p0, 2);
        p1 += __shfl_xor_sync(0xffffffffu, p1, 1);
        p1 += __shfl_xor_sync(0xffffffffu, p1, 2);
        if (q == 0) {
            red[(mt * 16 + r0)     * 4 + nq] = p0;
            red[(mt * 16 + r0 + 8) * 4 + nq] = p1;
        }
        __syncthreads();

        if (t < MTILE) {
            int ng = base + t;
            if (ng < NODES) {
                float s = red[t * 4] + red[t * 4 + 1] +
                          red[t * 4 + 2] + red[t * 4 + 3] + b2v;
                if (SQUARE) { g_gsq[ng] = s * s; g_msg[ng] = 0.0f; }
                else        { out[ng] = s; }
            }
        }
        __syncthreads();
    }
#endif
}

// ---------------------------------------------------------------------------
// Edge pass: msg[dst] += W[e] * gsq[src]
// ---------------------------------------------------------------------------
__global__ void edge_kernel(const int* __restrict__ src,
                            const int* __restrict__ dst,
                            const float* __restrict__ W,
                            int n_edges)
{
    int i = blockIdx.x * blockDim.x + threadIdx.x;
    if (i < n_edges) {
        const float m = W[i] * g_gsq[src[i]];
        atomicAdd(&g_msg[dst[i]], m);
    }
}

// ---------------------------------------------------------------------------
extern "C" void kernel_launch(void* const* d_in, const int* in_sizes, int n_in,
                              void* d_out, int out_size)
{
    const float* v    = (const float*)d_in[0];
    const float* exc  = (const float*)d_in[1];
    const int*   esrc = (const int*)  d_in[2];
    const int*   edst = (const int*)  d_in[3];
    const float* a    = (const float*)d_in[4];
    const float* W    = (const float*)d_in[5];
    const float* g0w  = (const float*)d_in[6];
    const float* g0b  = (const float*)d_in[7];
    const float* g1w  = (const float*)d_in[8];
    const float* g1b  = (const float*)d_in[9];
    const float* g2w  = (const float*)d_in[10];
    const float* g2b  = (const float*)d_in[11];
    const float* f0w  = (const float*)d_in[12];
    const float* f0b  = (const float*)d_in[13];
    const float* f1w  = (const float*)d_in[14];
    const float* f1b  = (const float*)d_in[15];
    const float* f2w  = (const float*)d_in[16];
    const float* f2b  = (const float*)d_in[17];
    float*       out  = (float*)d_out;

    const int n_edges = in_sizes[2];
    const int smem_bytes = (int)SMEM_BYTES;

    cudaFuncSetAttribute(mlp_kernel<3, true>,
                         cudaFuncAttributeMaxDynamicSharedMemorySize, smem_bytes);
    cudaFuncSetAttribute(mlp_kernel<5, false>,
                         cudaFuncAttributeMaxDynamicSharedMemorySize, smem_bytes);

    mlp_kernel<3, true><<<GRID, THREADS, smem_bytes>>>(
        v, a, nullptr, g0w, g0b, g1w, g1b, g2w, g2b, nullptr);

    edge_kernel<<<(n_edges + 255) / 256, 256>>>(esrc, edst, W, n_edges);

    mlp_kernel<5, false><<<GRID, THREADS, smem_bytes>>>(
        v, a, exc, f0w, f0b, f1w, f1b, f2w, f2b, out);
}

// round 12
// speedup vs baseline: 2.8725x; 1.1154x over previous
#include <cuda_runtime.h>
#include <cuda_bf16.h>
#include <math.h>
#include <stdint.h>

#define NODES   50000
#define HID     128
#define MTILE   128
#define NTILES  ((NODES + MTILE - 1) / MTILE)   // 391
#define THREADS 1024
#define GRID    148

// Does this device compilation expose tcgen05 (arch-specific sm_103a/sm_100a)?
#if defined(__CUDA_ARCH__) && \
    (defined(__CUDA_ARCH_FEAT_SM103_ALL) || defined(__CUDA_ARCH_FEAT_SM100_ALL))
#define TC_PATH 1
#else
#define TC_PATH 0
#endif

// ---- fallback (mma.sync) smem plane strides, uint2 units ----
#define H_S2U  68
#define W_S2U  68
#define X_S2U  12
#define W0_S2U 12

// ---- tcgen05 smem layout (byte offsets from 1024-aligned base) ----
// A planes double buffered: A0HI, A0LO, A1HI, A1LO; then BHI, BLO.
#define PB       32768                         // 128x128 bf16 blocked SW128
#define A_HI0    0
#define A_LO0    (PB)
#define A_HI1    (2 * PB)
#define A_LO1    (3 * PB)
#define BHI_OFF  (4 * PB)
#define BLO_OFF  (5 * PB)
#define W0S_OFF  (6 * PB)                      // 5*128 floats
#define B0S_OFF  (W0S_OFF + 5 * HID * 4)
#define B1S_OFF  (B0S_OFF + HID * 4)
#define W2S_OFF  (B1S_OFF + HID * 4)
#define RED_OFF  (W2S_OFF + HID * 4)           // 128*4 floats
#define PTR_OFF  (RED_OFF + MTILE * 4 * 4)
#define MBAR_OFF (PTR_OFF + 16)                // TWO mbarriers: +0, +8
#define TC_SMEM  (MBAR_OFF + 16 + 1024)        // + alignment slack  (~204 KB)

#define MMA_SMEM ((HID * W_S2U + MTILE * H_S2U + MTILE * X_S2U + HID * W0_S2U) * 8 + \
                  (3 * HID + MTILE * 4) * 4)
#define SMEM_BYTES (TC_SMEM > MMA_SMEM ? TC_SMEM : MMA_SMEM)

#define TMEM_COLS 512
// idesc kind::f16: F32 accum, bf16 x bf16, N=128, M=128
#define MMA_IDESC 0x8200490u

// Scratch (allocation-free rule: __device__ globals)
__device__ float g_gsq[NODES];
__device__ float g_msg[NODES];

// ---------------------------------------------------------------------------
// shared helpers
// ---------------------------------------------------------------------------
__device__ __forceinline__ float fast_tanh(float x) {
    float t = fminf(fmaxf(x * 2.885390082f, -30.0f), 30.0f);
    float e;
    asm("ex2.approx.f32 %0, %1;" : "=f"(e) : "f"(t));
    float r;
    asm("rcp.approx.f32 %0, %1;" : "=f"(r) : "f"(e + 1.0f));
    return (e - 1.0f) * r;
}
__device__ __forceinline__ float bfround(float x) {
    return __bfloat162float(__float2bfloat16(x));
}
__device__ __forceinline__ uint32_t bfpack(float f_even, float f_odd) {
    uint32_t r;
    asm("cvt.rn.bf16x2.f32 %0, %1, %2;" : "=r"(r) : "f"(f_odd), "f"(f_even));
    return r;
}
__device__ __forceinline__ uint2 split2(float e, float o) {
    float eh = bfround(e), oh = bfround(o);
    return make_uint2(bfpack(eh, oh), bfpack(e - eh, o - oh));
}
__device__ __forceinline__ uint32_t smem_u32(const void* p) {
    uint32_t r;
    asm("{ .reg .u64 t; cvta.to.shared.u64 t, %1; cvt.u32.u64 %0, t; }"
        : "=r"(r) : "l"(p));
    return r;
}

#if TC_PATH
// ---------------------------------------------------------------------------
// tcgen05 helpers
// ---------------------------------------------------------------------------
// blocked SW128 byte offset for bf16 tile [128 rows x 128 cols]
__device__ __forceinline__ uint32_t blk_off(int row, int col) {
    uint32_t off = (uint32_t)(((row >> 3) + ((col >> 6) << 4)) << 10)
                 + ((row & 7) << 7) + ((col & 63) << 1);
    return off ^ ((off >> 3) & 0x70);
}
__device__ __forceinline__ uint64_t make_desc(uint32_t saddr) {
    return ((uint64_t)2 << 61) | ((uint64_t)1 << 46) |
           ((uint64_t)64 << 32) | ((uint64_t)1 << 16) |
           (((uint64_t)(saddr >> 4)) & 0x3FFF);
}
__device__ __forceinline__ void tc_mma_f16_ss(uint32_t d_tmem, uint64_t a_desc,
                                              uint64_t b_desc, uint32_t en) {
    asm volatile(
        "{\n\t"
        ".reg .pred p;\n\t"
        "setp.ne.u32 p, %4, 0;\n\t"
        "tcgen05.mma.cta_group::1.kind::f16 [%0], %1, %2, %3, "
        "{%5, %5, %5, %5}, p;\n\t"
        "}"
        :: "r"(d_tmem), "l"(a_desc), "l"(b_desc), "r"(MMA_IDESC),
           "r"(en), "r"(0u)
        : "memory");
}
__device__ __forceinline__ void mbar_wait(uint32_t mbar, uint32_t parity) {
    asm volatile(
        "{\n\t"
        ".reg .pred P;\n\t"
        "WAIT_%=:\n\t"
        "mbarrier.try_wait.parity.acquire.cta.shared::cta.b64 P, [%0], %1, 0x989680;\n\t"
        "@!P bra.uni WAIT_%=;\n\t"
        "}" :: "r"(mbar), "r"(parity) : "memory");
}
// issue one bf16x3 K=128 MMA group into d_tmem, then commit to mbar
__device__ __forceinline__ void issue_mma_group(uint32_t d_tmem,
                                                uint64_t dAhi, uint64_t dAlo,
                                                uint64_t dBhi, uint64_t dBlo,
                                                uint32_t mbar) {
    asm volatile("fence.proxy.async.shared::cta;" ::: "memory");
    #pragma unroll
    for (int ks = 0; ks < 8; ks++) {
        uint64_t doff = (ks < 4) ? (uint64_t)(ks * 2)
                                 : (uint64_t)(1024 + (ks - 4) * 2);
        tc_mma_f16_ss(d_tmem, dAlo + doff, dBhi + doff, ks > 0 ? 1u : 0u);
        tc_mma_f16_ss(d_tmem, dAhi + doff, dBlo + doff, 1u);
        tc_mma_f16_ss(d_tmem, dAhi + doff, dBhi + doff, 1u);
    }
    asm volatile(
        "tcgen05.commit.cta_group::1.mbarrier::arrive::one.shared::cluster.b64 [%0];"
        :: "r"(mbar) : "memory");
}
#else
// ---------------------------------------------------------------------------
// mma.sync helper (fallback)
// ---------------------------------------------------------------------------
__device__ __forceinline__ void mma16(float* c, const uint32_t* a, const uint32_t* b) {
    asm volatile(
        "mma.sync.aligned.m16n8k16.row.col.f32.bf16.bf16.f32 "
        "{%0,%1,%2,%3}, {%4,%5,%6,%7}, {%8,%9}, {%0,%1,%2,%3};"
        : "+f"(c[0]), "+f"(c[1]), "+f"(c[2]), "+f"(c[3])
        : "r"(a[0]), "r"(a[1]), "r"(a[2]), "r"(a[3]),
          "r"(b[0]), "r"(b[1]));
}
#endif

// ---------------------------------------------------------------------------
// Persistent fused 3-layer MLP (body chosen by TC_PATH)
// ---------------------------------------------------------------------------
template <int IN_DIM, bool SQUARE>
__global__ void __launch_bounds__(THREADS, 1) mlp_kernel(
    const float* __restrict__ v,
    const float* __restrict__ a,
    const float* __restrict__ exc,
    const float* __restrict__ w0, const float* __restrict__ b0,
    const float* __restrict__ w1, const float* __restrict__ b1,
    const float* __restrict__ w2, const float* __restrict__ b2,
    float* __restrict__ out)
{
#if TC_PATH
    // ============ tcgen05, software-pipelined across node tiles ============
    extern __shared__ char smraw[];
    const uint32_t raw32 = smem_u32(smraw);
    const uint32_t base  = (raw32 + 1023) & ~1023u;
    char* smb = smraw + (base - raw32);

    float* w0s = (float*)(smb + W0S_OFF);
    float* b0s = (float*)(smb + B0S_OFF);
    float* b1s = (float*)(smb + B1S_OFF);
    float* w2s = (float*)(smb + W2S_OFF);
    float* red = (float*)(smb + RED_OFF);

    const int t   = threadIdx.x;
    const int wrp = t >> 5, lane = t & 31;

    if (wrp == 0) {
        asm volatile(
            "tcgen05.alloc.cta_group::1.sync.aligned.shared::cta.b32 [%0], %1;"
            :: "r"(base + PTR_OFF), "r"(TMEM_COLS) : "memory");
    }
    if (t == 0) {
        // one mbarrier per pipeline buffer -> unambiguous phase parity
        asm volatile("mbarrier.init.shared.b64 [%0], 1;"
                     :: "r"(base + MBAR_OFF) : "memory");
        asm volatile("mbarrier.init.shared.b64 [%0], 1;"
                     :: "r"(base + MBAR_OFF + 8) : "memory");
    }

    // stage once: W1^T -> Bhi/Blo planes; w0, biases
    for (int i = t; i < HID * HID / 2; i += THREADS) {
        int kp = i >> 7, n = i & 127;
        float e  = w1[(2 * kp)     * HID + n];
        float o  = w1[(2 * kp + 1) * HID + n];
        float eh = bfround(e), oh = bfround(o);
        uint32_t off = blk_off(n, 2 * kp);
        *(uint32_t*)(smb + BHI_OFF + off) = bfpack(eh, oh);
        *(uint32_t*)(smb + BLO_OFF + off) = bfpack(e - eh, o - oh);
    }
    for (int i = t; i < IN_DIM * HID; i += THREADS) w0s[i] = w0[i];
    if (t < HID) { b0s[t] = b0[t]; b1s[t] = b1[t]; w2s[t] = w2[t]; }
    const float b2v = b2[0];
    __syncthreads();

    uint32_t tmem_base;
    asm volatile("ld.shared.b32 %0, [%1];" : "=r"(tmem_base) : "r"(base + PTR_OFF));

    const uint64_t dAhi[2] = {make_desc(base + A_HI0), make_desc(base + A_HI1)};
    const uint64_t dAlo[2] = {make_desc(base + A_LO0), make_desc(base + A_LO1)};
    const uint64_t dBhi    = make_desc(base + BHI_OFF);
    const uint64_t dBlo    = make_desc(base + BLO_OFF);
    const uint32_t accoff[2] = {0u, 128u};
    const uint32_t mbar[2]   = {base + MBAR_OFF, base + MBAR_OFF + 8};

    // ---- layer0: direct gmem loads -> tanh -> split -> A planes[buf] ----
    auto layer0 = [&](int tbase, int buf) {
        char* ahi = smb + (buf ? A_HI1 : A_HI0);
        char* alo = smb + (buf ? A_LO1 : A_LO0);
        #pragma unroll
        for (int it = 0; it < MTILE * HID / 2 / THREADS; it++) {
            int i = it * THREADS + t;
            int node = i >> 6, jp = i & 63;
            int ng = tbase + node;
            bool ok = ng < NODES;
            float x0 = ok ? v[ng]         : 0.0f;
            float x1 = ok ? a[2 * ng]     : 0.0f;
            float x2 = ok ? a[2 * ng + 1] : 0.0f;
            float acc0 = b0s[2 * jp], acc1 = b0s[2 * jp + 1];
            acc0 += x0 * w0s[0 * HID + 2 * jp] + x1 * w0s[1 * HID + 2 * jp]
                  + x2 * w0s[2 * HID + 2 * jp];
            acc1 += x0 * w0s[0 * HID + 2 * jp + 1] + x1 * w0s[1 * HID + 2 * jp + 1]
                  + x2 * w0s[2 * HID + 2 * jp + 1];
            if (IN_DIM == 5) {
                float x3 = ok ? g_msg[ng] : 0.0f;
                float x4 = ok ? exc[ng]   : 0.0f;
                acc0 += x3 * w0s[3 * HID + 2 * jp] + x4 * w0s[4 * HID + 2 * jp];
                acc1 += x3 * w0s[3 * HID + 2 * jp + 1] + x4 * w0s[4 * HID + 2 * jp + 1];
            }
            float h0 = fast_tanh(acc0), h1 = fast_tanh(acc1);
            float h0h = bfround(h0), h1h = bfround(h1);
            uint32_t off = blk_off(node, 2 * jp);
            *(uint32_t*)(ahi + off) = bfpack(h0h, h1h);
            *(uint32_t*)(alo + off) = bfpack(h0 - h0h, h1 - h1h);
        }
    };

    uint32_t parity[2] = {0u, 0u};
    int tile = blockIdx.x;
    int buf  = 0;

    if (tile < NTILES) {
        layer0(tile * MTILE, buf);
        __syncthreads();
        if (wrp == 0) {
            uint32_t one;
            asm volatile("{\n\t.reg .pred p;\n\telect.sync _|p, 0xFFFFFFFF;\n\t"
                         "selp.b32 %0, 1, 0, p;\n\t}" : "=r"(one));
            if (one) issue_mma_group(tmem_base + accoff[buf], dAhi[buf], dAlo[buf],
                                     dBhi, dBlo, mbar[buf]);
        }
    }

    while (tile < NTILES) {
        const int next  = tile + GRID;
        const int nbuf  = buf ^ 1;
        const bool more = next < NTILES;

        // overlap: layer0 of next tile while MMA(tile) runs
        if (more) {
            layer0(next * MTILE, nbuf);
            __syncthreads();
            if (wrp == 0) {
                uint32_t one;
                asm volatile("{\n\t.reg .pred p;\n\telect.sync _|p, 0xFFFFFFFF;\n\t"
                             "selp.b32 %0, 1, 0, p;\n\t}" : "=r"(one));
                if (one) issue_mma_group(tmem_base + accoff[nbuf], dAhi[nbuf],
                                         dAlo[nbuf], dBhi, dBlo, mbar[nbuf]);
            }
        }

        // wait for MMA(tile) on THIS buffer's mbarrier, then epilogue
        mbar_wait(mbar[buf], parity[buf]);
        parity[buf] ^= 1u;
        asm volatile("tcgen05.fence::after_thread_sync;" ::: "memory");

        if (wrp < 16) {
            const int sub = wrp & 3;
            const int cg  = wrp >> 2;
            uint32_t dr[32];
            asm volatile(
                "tcgen05.ld.sync.aligned.32x32b.x32.b32 "
                "{%0,%1,%2,%3,%4,%5,%6,%7,%8,%9,%10,%11,%12,%13,%14,%15,"
                "%16,%17,%18,%19,%20,%21,%22,%23,%24,%25,%26,%27,%28,%29,%30,%31}, [%32];"
                : "=r"(dr[0]),  "=r"(dr[1]),  "=r"(dr[2]),  "=r"(dr[3]),
                  "=r"(dr[4]),  "=r"(dr[5]),  "=r"(dr[6]),  "=r"(dr[7]),
                  "=r"(dr[8]),  "=r"(dr[9]),  "=r"(dr[10]), "=r"(dr[11]),
                  "=r"(dr[12]), "=r"(dr[13]), "=r"(dr[14]), "=r"(dr[15]),
                  "=r"(dr[16]), "=r"(dr[17]), "=r"(dr[18]), "=r"(dr[19]),
                  "=r"(dr[20]), "=r"(dr[21]), "=r"(dr[22]), "=r"(dr[23]),
                  "=r"(dr[24]), "=r"(dr[25]), "=r"(dr[26]), "=r"(dr[27]),
                  "=r"(dr[28]), "=r"(dr[29]), "=r"(dr[30]), "=r"(dr[31])
                : "r"(tmem_base + accoff[buf] + cg * 32));
            asm volatile("tcgen05.wait::ld.sync.aligned;" ::: "memory");

            float p = 0.0f;
            #pragma unroll
            for (int c = 0; c < 32; c++) {
                int col = cg * 32 + c;
                p += fast_tanh(__uint_as_float(dr[c]) + b1s[col]) * w2s[col];
            }
            red[(sub * 32 + lane) * 4 + cg] = p;
            asm volatile("tcgen05.fence::before_thread_sync;" ::: "memory");
        }
        __syncthreads();

        if (t < MTILE) {
            int ng = tile * MTILE + t;
            if (ng < NODES) {
                float s = red[t * 4] + red[t * 4 + 1] +
                          red[t * 4 + 2] + red[t * 4 + 3] + b2v;
                if (SQUARE) { g_gsq[ng] = s * s; g_msg[ng] = 0.0f; }
                else        { out[ng] = s; }
            }
        }

        tile = next;
        buf  = nbuf;
        if (more) __syncthreads();   // protect red before next epilogue writes
    }

    __syncthreads();
    if (t == 0) {
        asm volatile("mbarrier.inval.shared.b64 [%0];"
                     :: "r"(base + MBAR_OFF) : "memory");
        asm volatile("mbarrier.inval.shared.b64 [%0];"
                     :: "r"(base + MBAR_OFF + 8) : "memory");
    }
    __syncthreads();
    if (wrp == 0) {
        asm volatile("tcgen05.relinquish_alloc_permit.cta_group::1.sync.aligned;");
        asm volatile("tcgen05.dealloc.cta_group::1.sync.aligned.b32 %0, %1;"
                     :: "r"(tmem_base), "r"(TMEM_COLS));
    }

#else
    // ================== fallback: round-8 mma.sync body ====================
    extern __shared__ float sm[];
    uint2* Wt2 = (uint2*)sm;
    uint2* Hs2 = Wt2 + HID * W_S2U;
    uint2* Xs2 = Hs2 + MTILE * H_S2U;
    uint2* Wt0 = Xs2 + MTILE * X_S2U;
    float* b0s = (float*)(Wt0 + HID * W0_S2U);
    float* b1s = b0s + HID;
    float* w2s = b1s + HID;
    float* red = w2s + HID;

    const int t    = threadIdx.x;
    const int wrp  = t >> 5, lane = t & 31;
    const int mt   = wrp & 7, nq = wrp >> 3;
    const int r0   = lane >> 2, q = lane & 3;

    for (int i = t; i < HID * HID / 2; i += THREADS) {
        int j = i >> 7, n = i & 127;
        Wt2[n * W_S2U + j] = split2(w1[(2 * j) * HID + n],
                                    w1[(2 * j + 1) * HID + n]);
    }
    {
        int n = t & 127, j = t >> 7;
        float e = (2 * j     < IN_DIM) ? w0[(2 * j)     * HID + n] : 0.0f;
        float o = (2 * j + 1 < IN_DIM) ? w0[(2 * j + 1) * HID + n] : 0.0f;
        Wt0[n * W0_S2U + j] = split2(e, o);
    }
    if (t < HID) { b0s[t] = b0[t]; b1s[t] = b1[t]; w2s[t] = w2[t]; }
    const float b2v = b2[0];
    __syncthreads();

    for (int tile = blockIdx.x; tile < NTILES; tile += GRID) {
        const int base = tile * MTILE;

        if (t < MTILE) {
            int ng = base + t;
            bool ok = ng < NODES;
            float x[5];
            x[0] = ok ? v[ng]         : 0.0f;
            x[1] = ok ? a[2 * ng]     : 0.0f;
            x[2] = ok ? a[2 * ng + 1] : 0.0f;
            x[3] = (IN_DIM == 5 && ok) ? g_msg[ng] : 0.0f;
            x[4] = (IN_DIM == 5 && ok) ? exc[ng]   : 0.0f;
            uint2* X = &Xs2[t * X_S2U];
            #pragma unroll
            for (int j = 0; j < 8; j++) {
                float e = (2 * j     < 5) ? x[2 * j]     : 0.0f;
                float o = (2 * j + 1 < 5) ? x[2 * j + 1] : 0.0f;
                X[j] = split2(e, o);
            }
        }
        __syncthreads();

        {
            float C0[4][4];
            #pragma unroll
            for (int i = 0; i < 4; i++) {
                C0[i][0] = 0.f; C0[i][1] = 0.f; C0[i][2] = 0.f; C0[i][3] = 0.f;
            }
            const uint2* X0 = &Xs2[(mt * 16 + r0) * X_S2U];
            const uint2* X1 = X0 + 8 * X_S2U;
            uint2 a0 = X0[q], a1 = X1[q], a2 = X0[q + 4], a3 = X1[q + 4];
            uint32_t Ahi[4] = {a0.x, a1.x, a2.x, a3.x};
            uint32_t Alo[4] = {a0.y, a1.y, a2.y, a3.y};
            #pragma unroll
            for (int nt = 0; nt < 4; nt++) {
                const uint2* Bp = &Wt0[(nq * 32 + nt * 8 + r0) * W0_S2U];
                uint2 b0v = Bp[q], b1v = Bp[q + 4];
                uint32_t Bhi[2] = {b0v.x, b1v.x};
                uint32_t Blo[2] = {b0v.y, b1v.y};
                mma16(C0[nt], Alo, Bhi);
                mma16(C0[nt], Ahi, Blo);
                mma16(C0[nt], Ahi, Bhi);
            }
            #pragma unroll
            for (int nt = 0; nt < 4; nt++) {
                const int col0 = nq * 32 + nt * 8 + q * 2;
                const float bb0 = b0s[col0], bb1 = b0s[col0 + 1];
                float h00 = fast_tanh(C0[nt][0] + bb0);
                float h01 = fast_tanh(C0[nt][1] + bb1);
                float h10 = fast_tanh(C0[nt][2] + bb0);
                float h11 = fast_tanh(C0[nt][3] + bb1);
                const int jp = nq * 16 + nt * 4 + q;
                Hs2[(mt * 16 + r0)     * H_S2U + jp] = split2(h00, h01);
                Hs2[(mt * 16 + r0 + 8) * H_S2U + jp] = split2(h10, h11);
            }
        }
        __syncthreads();

        float C[4][4];
        #pragma unroll
        for (int i = 0; i < 4; i++) {
            C[i][0] = 0.f; C[i][1] = 0.f; C[i][2] = 0.f; C[i][3] = 0.f;
        }
        const uint2* Arow0 = &Hs2[(mt * 16 + r0) * H_S2U];
        const uint2* Arow1 = Arow0 + 8 * H_S2U;

        #pragma unroll
        for (int ks = 0; ks < 8; ks++) {
            const int jb = ks * 8;
            uint2 a0 = Arow0[jb + q];
            uint2 a1 = Arow1[jb + q];
            uint2 a2 = Arow0[jb + q + 4];
            uint2 a3 = Arow1[jb + q + 4];
            uint32_t Ahi[4] = {a0.x, a1.x, a2.x, a3.x};
            uint32_t Alo[4] = {a0.y, a1.y, a2.y, a3.y};
            #pragma unroll
            for (int nt = 0; nt < 4; nt++) {
                const uint2* Bp = &Wt2[(nq * 32 + nt * 8 + r0) * W_S2U + jb];
                uint2 b0v = Bp[q];
                uint2 b1v = Bp[q + 4];
                uint32_t Bhi[2] = {b0v.x, b1v.x};
                uint32_t Blo[2] = {b0v.y, b1v.y};
                mma16(C[nt], Alo, Bhi);
                mma16(C[nt], Ahi, Blo);
                mma16(C[nt], Ahi, Bhi);
            }
        }

        float p0 = 0.f, p1 = 0.f;
        #pragma unroll
        for (int nt = 0; nt < 4; nt++) {
            const int c0 = nq * 32 + nt * 8 + q * 2;
            const float bb0 = b1s[c0], bb1 = b1s[c0 + 1];
            const float ww0 = w2s[c0], ww1 = w2s[c0 + 1];
            p0 += fast_tanh(C[nt][0] + bb0) * ww0 + fast_tanh(C[nt][1] + bb1) * ww1;
            p1 += fast_tanh(C[nt][2] + bb0) * ww0 + fast_tanh(C[nt][3] + bb1) * ww1;
        }
        p0 += __shfl_xor_sync(0xffffffffu, p0, 1);
        p0 += __shfl_xor_sync(0xffffffffu, p0, 2);
        p1 += __shfl_xor_sync(0xffffffffu, p1, 1);
        p1 += __shfl_xor_sync(0xffffffffu, p1, 2);
        if (q == 0) {
            red[(mt * 16 + r0)     * 4 + nq] = p0;
            red[(mt * 16 + r0 + 8) * 4 + nq] = p1;
        }
        __syncthreads();

        if (t < MTILE) {
            int ng = base + t;
            if (ng < NODES) {
                float s = red[t * 4] + red[t * 4 + 1] +
                          red[t * 4 + 2] + red[t * 4 + 3] + b2v;
                if (SQUARE) { g_gsq[ng] = s * s; g_msg[ng] = 0.0f; }
                else        { out[ng] = s; }
            }
        }
        __syncthreads();
    }
#endif
}

// ---------------------------------------------------------------------------
// Edge pass: msg[dst] += W[e] * gsq[src]  (4 edges/thread, vectorized)
// ---------------------------------------------------------------------------
__global__ void edge_kernel(const int* __restrict__ src,
                            const int* __restrict__ dst,
                            const float* __restrict__ W,
                            int n_edges)
{
    int i = blockIdx.x * blockDim.x + threadIdx.x;
    int i4 = i * 4;
    if (i4 + 3 < n_edges) {
        int4   s = *(const int4*)(src + i4);
        int4   d = *(const int4*)(dst + i4);
        float4 w = *(const float4*)(W   + i4);
        atomicAdd(&g_msg[d.x], w.x * g_gsq[s.x]);
        atomicAdd(&g_msg[d.y], w.y * g_gsq[s.y]);
        atomicAdd(&g_msg[d.z], w.z * g_gsq[s.z]);
        atomicAdd(&g_msg[d.w], w.w * g_gsq[s.w]);
    } else if (i4 < n_edges) {
        for (int j = i4; j < n_edges; j++)
            atomicAdd(&g_msg[dst[j]], W[j] * g_gsq[src[j]]);
    }
}

// ---------------------------------------------------------------------------
extern "C" void kernel_launch(void* const* d_in, const int* in_sizes, int n_in,
                              void* d_out, int out_size)
{
    const float* v    = (const float*)d_in[0];
    const float* exc  = (const float*)d_in[1];
    const int*   esrc = (const int*)  d_in[2];
    const int*   edst = (const int*)  d_in[3];
    const float* a    = (const float*)d_in[4];
    const float* W    = (const float*)d_in[5];
    const float* g0w  = (const float*)d_in[6];
    const float* g0b  = (const float*)d_in[7];
    const float* g1w  = (const float*)d_in[8];
    const float* g1b  = (const float*)d_in[9];
    const float* g2w  = (const float*)d_in[10];
    const float* g2b  = (const float*)d_in[11];
    const float* f0w  = (const float*)d_in[12];
    const float* f0b  = (const float*)d_in[13];
    const float* f1w  = (const float*)d_in[14];
    const float* f1b  = (const float*)d_in[15];
    const float* f2w  = (const float*)d_in[16];
    const float* f2b  = (const float*)d_in[17];
    float*       out  = (float*)d_out;

    const int n_edges = in_sizes[2];
    const int smem_bytes = (int)SMEM_BYTES;

    cudaFuncSetAttribute(mlp_kernel<3, true>,
                         cudaFuncAttributeMaxDynamicSharedMemorySize, smem_bytes);
    cudaFuncSetAttribute(mlp_kernel<5, false>,
                         cudaFuncAttributeMaxDynamicSharedMemorySize, smem_bytes);

    mlp_kernel<3, true><<<GRID, THREADS, smem_bytes>>>(
        v, a, nullptr, g0w, g0b, g1w, g1b, g2w, g2b, nullptr);

    const int n4 = (n_edges + 3) / 4;
    edge_kernel<<<(n4 + 255) / 256, 256>>>(esrc, edst, W, n_edges);

    mlp_kernel<5, false><<<GRID, THREADS, smem_bytes>>>(
        v, a, exc, f0w, f0b, f1w, f1b, f2w, f2b, out);
}

// round 13
// speedup vs baseline: 3.4111x; 1.1875x over previous
#include <cuda_runtime.h>
#include <cuda_bf16.h>
#include <math.h>
#include <stdint.h>

#define NODES   50000
#define HID     128
#define MTILE   128
#define NTILES  ((NODES + MTILE - 1) / MTILE)   // 391
#define THREADS 1024
#define GRID    148

// Does this device compilation expose tcgen05 (arch-specific sm_103a/sm_100a)?
#if defined(__CUDA_ARCH__) && \
    (defined(__CUDA_ARCH_FEAT_SM103_ALL) || defined(__CUDA_ARCH_FEAT_SM100_ALL))
#define TC_PATH 1
#else
#define TC_PATH 0
#endif

// ---- fallback (mma.sync) smem plane strides, uint2 units ----
#define H_S2U  68
#define W_S2U  68
#define X_S2U  12
#define W0_S2U 12

// ---- tcgen05 smem layout (byte offsets from 1024-aligned base) ----
#define PB       32768                         // 128x128 bf16 blocked SW128
#define A_HI0    0
#define A_LO0    (PB)
#define A_HI1    (2 * PB)
#define A_LO1    (3 * PB)
#define BHI_OFF  (4 * PB)
#define BLO_OFF  (5 * PB)
#define W0S_OFF  (6 * PB)                      // 5*128 floats
#define B0S_OFF  (W0S_OFF + 5 * HID * 4)
#define B1S_OFF  (B0S_OFF + HID * 4)
#define W2S_OFF  (B1S_OFF + HID * 4)
#define RED_OFF  (W2S_OFF + HID * 4)           // 128*4 floats
#define PTR_OFF  (RED_OFF + MTILE * 4 * 4)
#define MBAR_OFF (PTR_OFF + 16)                // TWO mbarriers: +0, +8
#define TC_SMEM  (MBAR_OFF + 16 + 1024)        // ~204 KB

#define MMA_SMEM ((HID * W_S2U + MTILE * H_S2U + MTILE * X_S2U + HID * W0_S2U) * 8 + \
                  (3 * HID + MTILE * 4) * 4)
#define SMEM_BYTES (TC_SMEM > MMA_SMEM ? TC_SMEM : MMA_SMEM)

#define TMEM_COLS 512
// idesc kind::f16: F32 accum, bf16 x bf16, N=128, M=128
#define MMA_IDESC 0x8200490u

// Scratch (allocation-free rule: __device__ globals)
__device__ float g_gsq[NODES];
__device__ float g_msg[NODES];

// ---------------------------------------------------------------------------
// shared helpers
// ---------------------------------------------------------------------------
__device__ __forceinline__ float fast_tanh(float x) {
    float t = fminf(fmaxf(x * 2.885390082f, -30.0f), 30.0f);
    float e;
    asm("ex2.approx.f32 %0, %1;" : "=f"(e) : "f"(t));
    float r;
    asm("rcp.approx.f32 %0, %1;" : "=f"(r) : "f"(e + 1.0f));
    return (e - 1.0f) * r;
}
__device__ __forceinline__ float bfround(float x) {
    return __bfloat162float(__float2bfloat16(x));
}
__device__ __forceinline__ uint32_t bfpack(float f_even, float f_odd) {
    uint32_t r;
    asm("cvt.rn.bf16x2.f32 %0, %1, %2;" : "=r"(r) : "f"(f_odd), "f"(f_even));
    return r;
}
__device__ __forceinline__ uint2 split2(float e, float o) {
    float eh = bfround(e), oh = bfround(o);
    return make_uint2(bfpack(eh, oh), bfpack(e - eh, o - oh));
}
__device__ __forceinline__ uint32_t smem_u32(const void* p) {
    uint32_t r;
    asm("{ .reg .u64 t; cvta.to.shared.u64 t, %1; cvt.u32.u64 %0, t; }"
        : "=r"(r) : "l"(p));
    return r;
}

#if TC_PATH
// ---------------------------------------------------------------------------
// tcgen05 helpers
// ---------------------------------------------------------------------------
__device__ __forceinline__ uint32_t blk_off(int row, int col) {
    uint32_t off = (uint32_t)(((row >> 3) + ((col >> 6) << 4)) << 10)
                 + ((row & 7) << 7) + ((col & 63) << 1);
    return off ^ ((off >> 3) & 0x70);
}
__device__ __forceinline__ uint64_t make_desc(uint32_t saddr) {
    return ((uint64_t)2 << 61) | ((uint64_t)1 << 46) |
           ((uint64_t)64 << 32) | ((uint64_t)1 << 16) |
           (((uint64_t)(saddr >> 4)) & 0x3FFF);
}
__device__ __forceinline__ void tc_mma_f16_ss(uint32_t d_tmem, uint64_t a_desc,
                                              uint64_t b_desc, uint32_t en) {
    asm volatile(
        "{\n\t"
        ".reg .pred p;\n\t"
        "setp.ne.u32 p, %4, 0;\n\t"
        "tcgen05.mma.cta_group::1.kind::f16 [%0], %1, %2, %3, "
        "{%5, %5, %5, %5}, p;\n\t"
        "}"
        :: "r"(d_tmem), "l"(a_desc), "l"(b_desc), "r"(MMA_IDESC),
           "r"(en), "r"(0u)
        : "memory");
}
__device__ __forceinline__ void mbar_wait(uint32_t mbar, uint32_t parity) {
    asm volatile(
        "{\n\t"
        ".reg .pred P;\n\t"
        "WAIT_%=:\n\t"
        "mbarrier.try_wait.parity.acquire.cta.shared::cta.b64 P, [%0], %1, 0x989680;\n\t"
        "@!P bra.uni WAIT_%=;\n\t"
        "}" :: "r"(mbar), "r"(parity) : "memory");
}
__device__ __forceinline__ void issue_mma_group(uint32_t d_tmem,
                                                uint64_t dAhi, uint64_t dAlo,
                                                uint64_t dBhi, uint64_t dBlo,
                                                uint32_t mbar) {
    asm volatile("fence.proxy.async.shared::cta;" ::: "memory");
    #pragma unroll
    for (int ks = 0; ks < 8; ks++) {
        uint64_t doff = (ks < 4) ? (uint64_t)(ks * 2)
                                 : (uint64_t)(1024 + (ks - 4) * 2);
        tc_mma_f16_ss(d_tmem, dAlo + doff, dBhi + doff, ks > 0 ? 1u : 0u);
        tc_mma_f16_ss(d_tmem, dAhi + doff, dBlo + doff, 1u);
        tc_mma_f16_ss(d_tmem, dAhi + doff, dBhi + doff, 1u);
    }
    asm volatile(
        "tcgen05.commit.cta_group::1.mbarrier::arrive::one.shared::cluster.b64 [%0];"
        :: "r"(mbar) : "memory");
}
#else
__device__ __forceinline__ void mma16(float* c, const uint32_t* a, const uint32_t* b) {
    asm volatile(
        "mma.sync.aligned.m16n8k16.row.col.f32.bf16.bf16.f32 "
        "{%0,%1,%2,%3}, {%4,%5,%6,%7}, {%8,%9}, {%0,%1,%2,%3};"
        : "+f"(c[0]), "+f"(c[1]), "+f"(c[2]), "+f"(c[3])
        : "r"(a[0]), "r"(a[1]), "r"(a[2]), "r"(a[3]),
          "r"(b[0]), "r"(b[1]));
}
#endif

// ---------------------------------------------------------------------------
// Persistent fused 3-layer MLP (body chosen by TC_PATH)
// ---------------------------------------------------------------------------
template <int IN_DIM, bool SQUARE>
__global__ void __launch_bounds__(THREADS, 1) mlp_kernel(
    const float* __restrict__ v,
    const float* __restrict__ a,
    const float* __restrict__ exc,
    const float* __restrict__ w0, const float* __restrict__ b0,
    const float* __restrict__ w1, const float* __restrict__ b1,
    const float* __restrict__ w2, const float* __restrict__ b2,
    float* __restrict__ out)
{
#if TC_PATH
    // ============ tcgen05, software-pipelined across node tiles ============
    extern __shared__ char smraw[];
    const uint32_t raw32 = smem_u32(smraw);
    const uint32_t base  = (raw32 + 1023) & ~1023u;
    char* smb = smraw + (base - raw32);

    float* w0s = (float*)(smb + W0S_OFF);
    float* b0s = (float*)(smb + B0S_OFF);
    float* b1s = (float*)(smb + B1S_OFF);
    float* w2s = (float*)(smb + W2S_OFF);
    float* red = (float*)(smb + RED_OFF);

    const int t   = threadIdx.x;
    const int wrp = t >> 5, lane = t & 31;

    if (wrp == 0) {
        asm volatile(
            "tcgen05.alloc.cta_group::1.sync.aligned.shared::cta.b32 [%0], %1;"
            :: "r"(base + PTR_OFF), "r"(TMEM_COLS) : "memory");
    }
    if (t == 0) {
        asm volatile("mbarrier.init.shared.b64 [%0], 1;"
                     :: "r"(base + MBAR_OFF) : "memory");
        asm volatile("mbarrier.init.shared.b64 [%0], 1;"
                     :: "r"(base + MBAR_OFF + 8) : "memory");
    }

    // stage once: W1^T -> Bhi/Blo planes; w0, biases
    for (int i = t; i < HID * HID / 2; i += THREADS) {
        int kp = i >> 7, n = i & 127;
        float e  = w1[(2 * kp)     * HID + n];
        float o  = w1[(2 * kp + 1) * HID + n];
        float eh = bfround(e), oh = bfround(o);
        uint32_t off = blk_off(n, 2 * kp);
        *(uint32_t*)(smb + BHI_OFF + off) = bfpack(eh, oh);
        *(uint32_t*)(smb + BLO_OFF + off) = bfpack(e - eh, o - oh);
    }
    for (int i = t; i < IN_DIM * HID; i += THREADS) w0s[i] = w0[i];
    if (t < HID) { b0s[t] = b0[t]; b1s[t] = b1[t]; w2s[t] = w2[t]; }
    const float b2v = b2[0];
    __syncthreads();

    uint32_t tmem_base;
    asm volatile("ld.shared.b32 %0, [%1];" : "=r"(tmem_base) : "r"(base + PTR_OFF));

    const uint64_t dAhi[2] = {make_desc(base + A_HI0), make_desc(base + A_HI1)};
    const uint64_t dAlo[2] = {make_desc(base + A_LO0), make_desc(base + A_LO1)};
    const uint64_t dBhi    = make_desc(base + BHI_OFF);
    const uint64_t dBlo    = make_desc(base + BLO_OFF);
    const uint32_t accoff[2] = {0u, 128u};
    const uint32_t mbar[2]   = {base + MBAR_OFF, base + MBAR_OFF + 8};

    // layer0 thread mapping: one node per thread, gmem loads hoisted.
    //   node = (wrp)*4 + (lane & 3)   [warp covers 4 nodes]
    //   jpg  = lane >> 2              [8 col-pair groups]
    //   per it (0..7): jp = it*8 + jpg  -> cols 2jp, 2jp+1 (consecutive within warp)
    const int l0_node = wrp * 4 + (lane & 3);
    const int l0_jpg  = lane >> 2;

    auto layer0 = [&](int tbase, int buf) {
        char* ahi = smb + (buf ? A_HI1 : A_HI0);
        char* alo = smb + (buf ? A_LO1 : A_LO0);
        const int ng = tbase + l0_node;
        const bool ok = ng < NODES;
        const float x0 = ok ? v[ng]         : 0.0f;
        const float x1 = ok ? a[2 * ng]     : 0.0f;
        const float x2 = ok ? a[2 * ng + 1] : 0.0f;
        float x3 = 0.0f, x4 = 0.0f;
        if (IN_DIM == 5) {
            x3 = ok ? g_msg[ng] : 0.0f;
            x4 = ok ? exc[ng]   : 0.0f;
        }
        #pragma unroll
        for (int it = 0; it < 8; it++) {
            const int jp = it * 8 + l0_jpg;       // col pair index 0..63
            const int c0 = 2 * jp;
            float acc0 = b0s[c0],     acc1 = b0s[c0 + 1];
            acc0 += x0 * w0s[0 * HID + c0] + x1 * w0s[1 * HID + c0]
                  + x2 * w0s[2 * HID + c0];
            acc1 += x0 * w0s[0 * HID + c0 + 1] + x1 * w0s[1 * HID + c0 + 1]
                  + x2 * w0s[2 * HID + c0 + 1];
            if (IN_DIM == 5) {
                acc0 += x3 * w0s[3 * HID + c0] + x4 * w0s[4 * HID + c0];
                acc1 += x3 * w0s[3 * HID + c0 + 1] + x4 * w0s[4 * HID + c0 + 1];
            }
            float h0 = fast_tanh(acc0), h1 = fast_tanh(acc1);
            float h0h = bfround(h0), h1h = bfround(h1);
            uint32_t off = blk_off(l0_node, c0);
            *(uint32_t*)(ahi + off) = bfpack(h0h, h1h);
            *(uint32_t*)(alo + off) = bfpack(h0 - h0h, h1 - h1h);
        }
    };

    uint32_t parity[2] = {0u, 0u};
    int tile = blockIdx.x;
    int buf  = 0;

    if (tile < NTILES) {
        layer0(tile * MTILE, buf);
        __syncthreads();
        if (wrp == 0) {
            uint32_t one;
            asm volatile("{\n\t.reg .pred p;\n\telect.sync _|p, 0xFFFFFFFF;\n\t"
                         "selp.b32 %0, 1, 0, p;\n\t}" : "=r"(one));
            if (one) issue_mma_group(tmem_base + accoff[buf], dAhi[buf], dAlo[buf],
                                     dBhi, dBlo, mbar[buf]);
        }
    }

    while (tile < NTILES) {
        const int next  = tile + GRID;
        const int nbuf  = buf ^ 1;
        const bool more = next < NTILES;

        if (more) {
            layer0(next * MTILE, nbuf);
            __syncthreads();
            if (wrp == 0) {
                uint32_t one;
                asm volatile("{\n\t.reg .pred p;\n\telect.sync _|p, 0xFFFFFFFF;\n\t"
                             "selp.b32 %0, 1, 0, p;\n\t}" : "=r"(one));
                if (one) issue_mma_group(tmem_base + accoff[nbuf], dAhi[nbuf],
                                         dAlo[nbuf], dBhi, dBlo, mbar[nbuf]);
            }
        }

        mbar_wait(mbar[buf], parity[buf]);
        parity[buf] ^= 1u;
        asm volatile("tcgen05.fence::after_thread_sync;" ::: "memory");

        if (wrp < 16) {
            const int sub = wrp & 3;
            const int cg  = wrp >> 2;
            uint32_t dr[32];
            asm volatile(
                "tcgen05.ld.sync.aligned.32x32b.x32.b32 "
                "{%0,%1,%2,%3,%4,%5,%6,%7,%8,%9,%10,%11,%12,%13,%14,%15,"
                "%16,%17,%18,%19,%20,%21,%22,%23,%24,%25,%26,%27,%28,%29,%30,%31}, [%32];"
                : "=r"(dr[0]),  "=r"(dr[1]),  "=r"(dr[2]),  "=r"(dr[3]),
                  "=r"(dr[4]),  "=r"(dr[5]),  "=r"(dr[6]),  "=r"(dr[7]),
                  "=r"(dr[8]),  "=r"(dr[9]),  "=r"(dr[10]), "=r"(dr[11]),
                  "=r"(dr[12]), "=r"(dr[13]), "=r"(dr[14]), "=r"(dr[15]),
                  "=r"(dr[16]), "=r"(dr[17]), "=r"(dr[18]), "=r"(dr[19]),
                  "=r"(dr[20]), "=r"(dr[21]), "=r"(dr[22]), "=r"(dr[23]),
                  "=r"(dr[24]), "=r"(dr[25]), "=r"(dr[26]), "=r"(dr[27]),
                  "=r"(dr[28]), "=r"(dr[29]), "=r"(dr[30]), "=r"(dr[31])
                : "r"(tmem_base + accoff[buf] + cg * 32));
            asm volatile("tcgen05.wait::ld.sync.aligned;" ::: "memory");

            float p = 0.0f;
            #pragma unroll
            for (int c = 0; c < 32; c++) {
                int col = cg * 32 + c;
                p += fast_tanh(__uint_as_float(dr[c]) + b1s[col]) * w2s[col];
            }
            red[(sub * 32 + lane) * 4 + cg] = p;
            asm volatile("tcgen05.fence::before_thread_sync;" ::: "memory");
        }
        __syncthreads();

        if (t < MTILE) {
            int ng = tile * MTILE + t;
            if (ng < NODES) {
                float s = red[t * 4] + red[t * 4 + 1] +
                          red[t * 4 + 2] + red[t * 4 + 3] + b2v;
                if (SQUARE) { g_gsq[ng] = s * s; g_msg[ng] = 0.0f; }
                else        { out[ng] = s; }
            }
        }

        tile = next;
        buf  = nbuf;
        if (more) __syncthreads();   // protect red before next epilogue writes
    }

    __syncthreads();
    if (t == 0) {
        asm volatile("mbarrier.inval.shared.b64 [%0];"
                     :: "r"(base + MBAR_OFF) : "memory");
        asm volatile("mbarrier.inval.shared.b64 [%0];"
                     :: "r"(base + MBAR_OFF + 8) : "memory");
    }
    __syncthreads();
    if (wrp == 0) {
        asm volatile("tcgen05.relinquish_alloc_permit.cta_group::1.sync.aligned;");
        asm volatile("tcgen05.dealloc.cta_group::1.sync.aligned.b32 %0, %1;"
                     :: "r"(tmem_base), "r"(TMEM_COLS));
    }

#else
    // ================== fallback: round-8 mma.sync body ====================
    extern __shared__ float sm[];
    uint2* Wt2 = (uint2*)sm;
    uint2* Hs2 = Wt2 + HID * W_S2U;
    uint2* Xs2 = Hs2 + MTILE * H_S2U;
    uint2* Wt0 = Xs2 + MTILE * X_S2U;
    float* b0s = (float*)(Wt0 + HID * W0_S2U);
    float* b1s = b0s + HID;
    float* w2s = b1s + HID;
    float* red = w2s + HID;

    const int t    = threadIdx.x;
    const int wrp  = t >> 5, lane = t & 31;
    const int mt   = wrp & 7, nq = wrp >> 3;
    const int r0   = lane >> 2, q = lane & 3;

    for (int i = t; i < HID * HID / 2; i += THREADS) {
        int j = i >> 7, n = i & 127;
        Wt2[n * W_S2U + j] = split2(w1[(2 * j) * HID + n],
                                    w1[(2 * j + 1) * HID + n]);
    }
    {
        int n = t & 127, j = t >> 7;
        float e = (2 * j     < IN_DIM) ? w0[(2 * j)     * HID + n] : 0.0f;
        float o = (2 * j + 1 < IN_DIM) ? w0[(2 * j + 1) * HID + n] : 0.0f;
        Wt0[n * W0_S2U + j] = split2(e, o);
    }
    if (t < HID) { b0s[t] = b0[t]; b1s[t] = b1[t]; w2s[t] = w2[t]; }
    const float b2v = b2[0];
    __syncthreads();

    for (int tile = blockIdx.x; tile < NTILES; tile += GRID) {
        const int base = tile * MTILE;

        if (t < MTILE) {
            int ng = base + t;
            bool ok = ng < NODES;
            float x[5];
            x[0] = ok ? v[ng]         : 0.0f;
            x[1] = ok ? a[2 * ng]     : 0.0f;
            x[2] = ok ? a[2 * ng + 1] : 0.0f;
            x[3] = (IN_DIM == 5 && ok) ? g_msg[ng] : 0.0f;
            x[4] = (IN_DIM == 5 && ok) ? exc[ng]   : 0.0f;
            uint2* X = &Xs2[t * X_S2U];
            #pragma unroll
            for (int j = 0; j < 8; j++) {
                float e = (2 * j     < 5) ? x[2 * j]     : 0.0f;
                float o = (2 * j + 1 < 5) ? x[2 * j + 1] : 0.0f;
                X[j] = split2(e, o);
            }
        }
        __syncthreads();

        {
            float C0[4][4];
            #pragma unroll
            for (int i = 0; i < 4; i++) {
                C0[i][0] = 0.f; C0[i][1] = 0.f; C0[i][2] = 0.f; C0[i][3] = 0.f;
            }
            const uint2* X0 = &Xs2[(mt * 16 + r0) * X_S2U];
            const uint2* X1 = X0 + 8 * X_S2U;
            uint2 a0 = X0[q], a1 = X1[q], a2 = X0[q + 4], a3 = X1[q + 4];
            uint32_t Ahi[4] = {a0.x, a1.x, a2.x, a3.x};
            uint32_t Alo[4] = {a0.y, a1.y, a2.y, a3.y};
            #pragma unroll
            for (int nt = 0; nt < 4; nt++) {
                const uint2* Bp = &Wt0[(nq * 32 + nt * 8 + r0) * W0_S2U];
                uint2 b0v = Bp[q], b1v = Bp[q + 4];
                uint32_t Bhi[2] = {b0v.x, b1v.x};
                uint32_t Blo[2] = {b0v.y, b1v.y};
                mma16(C0[nt], Alo, Bhi);
                mma16(C0[nt], Ahi, Blo);
                mma16(C0[nt], Ahi, Bhi);
            }
            #pragma unroll
            for (int nt = 0; nt < 4; nt++) {
                const int col0 = nq * 32 + nt * 8 + q * 2;
                const float bb0 = b0s[col0], bb1 = b0s[col0 + 1];
                float h00 = fast_tanh(C0[nt][0] + bb0);
                float h01 = fast_tanh(C0[nt][1] + bb1);
                float h10 = fast_tanh(C0[nt][2] + bb0);
                float h11 = fast_tanh(C0[nt][3] + bb1);
                const int jp = nq * 16 + nt * 4 + q;
                Hs2[(mt * 16 + r0)     * H_S2U + jp] = split2(h00, h01);
                Hs2[(mt * 16 + r0 + 8) * H_S2U + jp] = split2(h10, h11);
            }
        }
        __syncthreads();

        float C[4][4];
        #pragma unroll
        for (int i = 0; i < 4; i++) {
            C[i][0] = 0.f; C[i][1] = 0.f; C[i][2] = 0.f; C[i][3] = 0.f;
        }
        const uint2* Arow0 = &Hs2[(mt * 16 + r0) * H_S2U];
        const uint2* Arow1 = Arow0 + 8 * H_S2U;

        #pragma unroll
        for (int ks = 0; ks < 8; ks++) {
            const int jb = ks * 8;
            uint2 a0 = Arow0[jb + q];
            uint2 a1 = Arow1[jb + q];
            uint2 a2 = Arow0[jb + q + 4];
            uint2 a3 = Arow1[jb + q + 4];
            uint32_t Ahi[4] = {a0.x, a1.x, a2.x, a3.x};
            uint32_t Alo[4] = {a0.y, a1.y, a2.y, a3.y};
            #pragma unroll
            for (int nt = 0; nt < 4; nt++) {
                const uint2* Bp = &Wt2[(nq * 32 + nt * 8 + r0) * W_S2U + jb];
                uint2 b0v = Bp[q];
                uint2 b1v = Bp[q + 4];
                uint32_t Bhi[2] = {b0v.x, b1v.x};
                uint32_t Blo[2] = {b0v.y, b1v.y};
                mma16(C[nt], Alo, Bhi);
                mma16(C[nt], Ahi, Blo);
                mma16(C[nt], Ahi, Bhi);
            }
        }

        float p0 = 0.f, p1 = 0.f;
        #pragma unroll
        for (int nt = 0; nt < 4; nt++) {
            const int c0 = nq * 32 + nt * 8 + q * 2;
            const float bb0 = b1s[c0], bb1 = b1s[c0 + 1];
            const float ww0 = w2s[c0], ww1 = w2s[c0 + 1];
            p0 += fast_tanh(C[nt][0] + bb0) * ww0 + fast_tanh(C[nt][1] + bb1) * ww1;
            p1 += fast_tanh(C[nt][2] + bb0) * ww0 + fast_tanh(C[nt][3] + bb1) * ww1;
        }
        p0 += __shfl_xor_sync(0xffffffffu, p0, 1);
        p0 += __shfl_xor_sync(0xffffffffu, p0, 2);
        p1 += __shfl_xor_sync(0xffffffffu, p1, 1);
        p1 += __shfl_xor_sync(0xffffffffu, p1, 2);
        if (q == 0) {
            red[(mt * 16 + r0)     * 4 + nq] = p0;
            red[(mt * 16 + r0 + 8) * 4 + nq] = p1;
        }
        __syncthreads();

        if (t < MTILE) {
            int ng = base + t;
            if (ng < NODES) {
                float s = red[t * 4] + red[t * 4 + 1] +
                          red[t * 4 + 2] + red[t * 4 + 3] + b2v;
                if (SQUARE) { g_gsq[ng] = s * s; g_msg[ng] = 0.0f; }
                else        { out[ng] = s; }
            }
        }
        __syncthreads();
    }
#endif
}

// ---------------------------------------------------------------------------
// Edge pass: msg[dst] += W[e] * gsq[src]  (4 edges/thread, vectorized)
// ---------------------------------------------------------------------------
__global__ void edge_kernel(const int* __restrict__ src,
                            const int* __restrict__ dst,
                            const float* __restrict__ W,
                            int n_edges)
{
    int i = blockIdx.x * blockDim.x + threadIdx.x;
    int i4 = i * 4;
    if (i4 + 3 < n_edges) {
        int4   s = *(const int4*)(src + i4);
        int4   d = *(const int4*)(dst + i4);
        float4 w = *(const float4*)(W   + i4);
        atomicAdd(&g_msg[d.x], w.x * g_gsq[s.x]);
        atomicAdd(&g_msg[d.y], w.y * g_gsq[s.y]);
        atomicAdd(&g_msg[d.z], w.z * g_gsq[s.z]);
        atomicAdd(&g_msg[d.w], w.w * g_gsq[s.w]);
    } else if (i4 < n_edges) {
        for (int j = i4; j < n_edges; j++)
            atomicAdd(&g_msg[dst[j]], W[j] * g_gsq[src[j]]);
    }
}

// ---------------------------------------------------------------------------
extern "C" void kernel_launch(void* const* d_in, const int* in_sizes, int n_in,
                              void* d_out, int out_size)
{
    const float* v    = (const float*)d_in[0];
    const float* exc  = (const float*)d_in[1];
    const int*   esrc = (const int*)  d_in[2];
    const int*   edst = (const int*)  d_in[3];
    const float* a    = (const float*)d_in[4];
    const float* W    = (const float*)d_in[5];
    const float* g0w  = (const float*)d_in[6];
    const float* g0b  = (const float*)d_in[7];
    const float* g1w  = (const float*)d_in[8];
    const float* g1b  = (const float*)d_in[9];
    const float* g2w  = (const float*)d_in[10];
    const float* g2b  = (const float*)d_in[11];
    const float* f0w  = (const float*)d_in[12];
    const float* f0b  = (const float*)d_in[13];
    const float* f1w  = (const float*)d_in[14];
    const float* f1b  = (const float*)d_in[15];
    const float* f2w  = (const float*)d_in[16];
    const float* f2b  = (const float*)d_in[17];
    float*       out  = (float*)d_out;

    const int n_edges = in_sizes[2];
    const int smem_bytes = (int)SMEM_BYTES;

    cudaFuncSetAttribute(mlp_kernel<3, true>,
                         cudaFuncAttributeMaxDynamicSharedMemorySize, smem_bytes);
    cudaFuncSetAttribute(mlp_kernel<5, false>,
                         cudaFuncAttributeMaxDynamicSharedMemorySize, smem_bytes);

    mlp_kernel<3, true><<<GRID, THREADS, smem_bytes>>>(
        v, a, nullptr, g0w, g0b, g1w, g1b, g2w, g2b, nullptr);

    const int n4 = (n_edges + 3) / 4;
    edge_kernel<<<(n4 + 255) / 256, 256>>>(esrc, edst, W, n_edges);

    mlp_kernel<5, false><<<GRID, THREADS, smem_bytes>>>(
        v, a, exc, f0w, f0b, f1w, f1b, f2w, f2b, out);
}